// round 13
// baseline (speedup 1.0000x reference)
#include <cuda_runtime.h>
#include <cuda_fp16.h>
#include <math.h>
#include <stdint.h>

// ---------------------------------------------------------------------------
// Scratch (device globals; no allocation allowed)
// ---------------------------------------------------------------------------
#define TOK 4096              // B*T = 4*1024
#define CDIM 1024
#define HID 4096

__device__ __half g_ln [TOK * CDIM];
__device__ __half g_qkv[TOK * 3072];
__device__ float  g_x1 [TOK * CDIM];
__device__ float  g_x2 [TOK * CDIM];
__device__ __half g_h1 [TOK * HID];
__device__ __half g_wt [2 * CDIM * 3072];   // per layer: [C=1024][3072] = Wq|Wk|Wv
__device__ __half g_w1 [CDIM * HID];
__device__ __half g_w2 [HID * CDIM];

#define NSLOTS 296            // 148 SMs x 2 CTAs/SM

// ---------------------------------------------------------------------------
// helpers
// ---------------------------------------------------------------------------
__device__ __forceinline__ void mma_f16(float c[4],
    uint32_t a0, uint32_t a1, uint32_t a2, uint32_t a3,
    uint32_t b0, uint32_t b1)
{
    asm volatile(
        "mma.sync.aligned.m16n8k16.row.col.f32.f16.f16.f32 "
        "{%0,%1,%2,%3}, {%4,%5,%6,%7}, {%8,%9}, {%0,%1,%2,%3};\n"
        : "+f"(c[0]), "+f"(c[1]), "+f"(c[2]), "+f"(c[3])
        : "r"(a0), "r"(a1), "r"(a2), "r"(a3), "r"(b0), "r"(b1));
}

__device__ __forceinline__ void ldsm_x4(uint32_t& r0, uint32_t& r1,
                                        uint32_t& r2, uint32_t& r3, uint32_t addr)
{
    asm volatile("ldmatrix.sync.aligned.m8n8.x4.shared.b16 {%0,%1,%2,%3}, [%4];"
        : "=r"(r0), "=r"(r1), "=r"(r2), "=r"(r3) : "r"(addr));
}
__device__ __forceinline__ void ldsm_x4t(uint32_t& r0, uint32_t& r1,
                                         uint32_t& r2, uint32_t& r3, uint32_t addr)
{
    asm volatile("ldmatrix.sync.aligned.m8n8.x4.trans.shared.b16 {%0,%1,%2,%3}, [%4];"
        : "=r"(r0), "=r"(r1), "=r"(r2), "=r"(r3) : "r"(addr));
}

__device__ __forceinline__ void cp16(uint32_t dst_smem, const void* src) {
    asm volatile("cp.async.cg.shared.global [%0], [%1], 16;\n"
        :: "r"(dst_smem), "l"(src));
}
#define CP_COMMIT() asm volatile("cp.async.commit_group;\n" ::: "memory")

// ---------------------------------------------------------------------------
// Fused weight transpose: six [H=16,C=1024,d=64] -> half cols of [C][3072]
// grid (4096, 6)
// ---------------------------------------------------------------------------
__global__ void wtrans6_kernel(
    const float* __restrict__ s0, const float* __restrict__ s1,
    const float* __restrict__ s2, const float* __restrict__ s3,
    const float* __restrict__ s4, const float* __restrict__ s5,
    __half* __restrict__ wt)
{
    const float* srcs[6] = {s0, s1, s2, s3, s4, s5};
    const int which = blockIdx.y;
    const float* W = srcs[which];
    __half* Wt = wt + (size_t)(which / 3) * (CDIM * 3072) + (which % 3) * 1024;
    int idx = blockIdx.x * 256 + threadIdx.x;       // 0 .. 1M-1
    int dd = idx & 63;
    int c  = (idx >> 6) & 1023;
    int h  = idx >> 16;
    Wt[(size_t)c * 3072 + h * 64 + dd] = __float2half(W[idx]);
}

// Convert W1 and W2 (4M floats each) to half. grid 8192 x 256, float4 each.
__global__ void wconv2_kernel(const float4* __restrict__ W1,
                              const float4* __restrict__ W2,
                              __half* __restrict__ w1, __half* __restrict__ w2)
{
    int i = blockIdx.x * 256 + threadIdx.x;         // 0 .. 2M-1
    const bool second = i >= (1 << 20);
    int j = second ? i - (1 << 20) : i;
    float4 v = second ? W2[j] : W1[j];
    __half2 h0 = __floats2half2_rn(v.x, v.y);
    __half2 h1 = __floats2half2_rn(v.z, v.w);
    uint2 u = make_uint2(*(uint32_t*)&h0, *(uint32_t*)&h1);
    if (second) ((uint2*)w2)[j] = u; else ((uint2*)w1)[j] = u;
}

// ---------------------------------------------------------------------------
// LayerNorm: one block per row of 1024; half output
// ---------------------------------------------------------------------------
__global__ __launch_bounds__(256) void ln_kernel(
    const float* __restrict__ x, const float* __restrict__ g,
    const float* __restrict__ b, __half* __restrict__ out)
{
    __shared__ float red[2][8];
    const int row = blockIdx.x;
    const int tid = threadIdx.x;
    const float4 xv = ((const float4*)(x + (size_t)row * 1024))[tid];
    float s  = xv.x + xv.y + xv.z + xv.w;
    float ss = xv.x*xv.x + xv.y*xv.y + xv.z*xv.z + xv.w*xv.w;
    #pragma unroll
    for (int off = 16; off; off >>= 1) {
        s  += __shfl_xor_sync(0xffffffffu, s,  off);
        ss += __shfl_xor_sync(0xffffffffu, ss, off);
    }
    const int warp = tid >> 5, lane = tid & 31;
    if (lane == 0) { red[0][warp] = s; red[1][warp] = ss; }
    __syncthreads();
    float st = 0.f, sst = 0.f;
    #pragma unroll
    for (int i = 0; i < 8; i++) { st += red[0][i]; sst += red[1][i]; }
    const float mean = st * (1.f / 1024.f);
    const float var  = sst * (1.f / 1024.f) - mean * mean;
    const float inv  = rsqrtf(var + 1e-5f);
    const float4 gv = ((const float4*)g)[tid];
    const float4 bv = ((const float4*)b)[tid];
    __half2 h0 = __floats2half2_rn((xv.x - mean) * inv * gv.x + bv.x,
                                   (xv.y - mean) * inv * gv.y + bv.y);
    __half2 h1 = __floats2half2_rn((xv.z - mean) * inv * gv.z + bv.z,
                                   (xv.w - mean) * inv * gv.w + bv.w);
    ((uint2*)(out + (size_t)row * 1024))[tid] =
        make_uint2(*(uint32_t*)&h0, *(uint32_t*)&h1);
}

// ---------------------------------------------------------------------------
// fp16 tensor-core GEMM, PERSISTENT CTAs, cp.async 4-stage.
//   C[M,N] = A[M,K] @ B[K,N]  (+ epilogue)
//   MODE 0: plain -> half out   MODE 1: +bias, relu -> half out
//   MODE 2: +bias +res -> float out
// CTA tile 128x128, BK=32, 128 thr = 4 warps (2Mx2N), warp tile 64x64,
// 2 CTAs/SM. grid = min(NSLOTS, ntiles); each CTA loops tiles with stride
// gridDim.x (removes wave-quantization tails). tile = by*NBX + bx.
// smem (halves): 4 stages x (A[128][40] + B[32][136]) = 75776 B
// ---------------------------------------------------------------------------
#define AP   40
#define BP   136
#define ASTG (128 * AP)
#define BSTG (32 * BP)
#define STG  (ASTG + BSTG)
template<int MODE>
__global__ __launch_bounds__(128, 2) void hgemm_kernel(
    const __half* __restrict__ A, const __half* __restrict__ B,
    const float* __restrict__ bias, const float* __restrict__ res,
    void* __restrict__ Cout, int M, int N, int K, int NBX, int NTILES)
{
    extern __shared__ __half sh[];
    const int tid  = threadIdx.x;
    const int warp = tid >> 5, lane = tid & 31;
    const int g  = lane >> 2, tq = lane & 3;
    const int wm = (warp >> 1) * 64;     // 0,64  (warp covers 64 M rows)
    const int wn = (warp & 1) * 64;      // 0,64
    const uint32_t sb = (uint32_t)__cvta_generic_to_shared(sh);

    for (int tile = blockIdx.x; tile < NTILES; tile += gridDim.x) {
        const int bx = tile % NBX, by = tile / NBX;
        const __half* Ag = A + (size_t)(by * 128) * K;
        const __half* Bg = B + bx * 128;

        __syncthreads();   // smem reuse guard across tile iterations

        auto stage = [&](int s) {
            const int k0 = s * 32;
            const uint32_t ab = sb + (uint32_t)((s & 3) * STG) * 2;
            const uint32_t bb = ab + ASTG * 2;
            #pragma unroll
            for (int i = 0; i < 4; i++) {               // A: 128 rows x 4 chunks
                int id = tid + (i << 7);
                int r = id >> 2, c = (id & 3) * 8;
                cp16(ab + (uint32_t)(r * AP + c) * 2, Ag + (size_t)r * K + k0 + c);
            }
            #pragma unroll
            for (int i = 0; i < 4; i++) {               // B: 32 rows x 16 chunks
                int id = tid + (i << 7);
                int r = id >> 4, c = (id & 15) * 8;
                cp16(bb + (uint32_t)(r * BP + c) * 2, Bg + (size_t)(k0 + r) * N + c);
            }
            CP_COMMIT();
        };

        float acc[4][8][4] = {};
        stage(0); stage(1); stage(2);

        const int NS = K / 32;
        for (int s = 0; s < NS; s++) {
            if (s < NS - 2)       asm volatile("cp.async.wait_group 2;\n" ::: "memory");
            else if (s == NS - 2) asm volatile("cp.async.wait_group 1;\n" ::: "memory");
            else                  asm volatile("cp.async.wait_group 0;\n" ::: "memory");
            __syncthreads();

            const uint32_t ab = sb + (uint32_t)((s & 3) * STG) * 2;
            const uint32_t bb = ab + ASTG * 2;
            #pragma unroll
            for (int ks = 0; ks < 2; ks++) {
                const int kb = ks * 16;
                uint32_t af[4][4];
                #pragma unroll
                for (int mi = 0; mi < 4; mi++) {
                    uint32_t addr = ab +
                        (uint32_t)((wm + mi * 16 + (lane & 15)) * AP + kb + (lane >> 4) * 8) * 2;
                    ldsm_x4(af[mi][0], af[mi][1], af[mi][2], af[mi][3], addr);
                }
                uint32_t bf[8][2];
                #pragma unroll
                for (int nj = 0; nj < 4; nj++) {
                    uint32_t addr = bb +
                        (uint32_t)((kb + (lane & 15)) * BP + wn + nj * 16 + (lane >> 4) * 8) * 2;
                    ldsm_x4t(bf[nj * 2][0], bf[nj * 2][1],
                             bf[nj * 2 + 1][0], bf[nj * 2 + 1][1], addr);
                }
                #pragma unroll
                for (int mi = 0; mi < 4; mi++)
                    #pragma unroll
                    for (int ni = 0; ni < 8; ni++)
                        mma_f16(acc[mi][ni], af[mi][0], af[mi][1], af[mi][2], af[mi][3],
                                bf[ni][0], bf[ni][1]);
            }
            if (s + 3 < NS) stage(s + 3);
        }

        #pragma unroll
        for (int mi = 0; mi < 4; mi++) {
            #pragma unroll
            for (int ni = 0; ni < 8; ni++) {
                const int row0 = by * 128 + wm + mi * 16 + g;
                const int col  = bx * 128 + wn + ni * 8 + 2 * tq;
                #pragma unroll
                for (int half_i = 0; half_i < 2; half_i++) {
                    const int row = row0 + half_i * 8;
                    float v0 = acc[mi][ni][half_i * 2 + 0];
                    float v1 = acc[mi][ni][half_i * 2 + 1];
                    if (MODE == 0) {
                        __half2 hv = __floats2half2_rn(v0, v1);
                        *(uint32_t*)((__half*)Cout + (size_t)row * N + col) = *(uint32_t*)&hv;
                    }
                    if (MODE == 1) {
                        v0 = fmaxf(v0 + bias[col], 0.f);
                        v1 = fmaxf(v1 + bias[col + 1], 0.f);
                        __half2 hv = __floats2half2_rn(v0, v1);
                        *(uint32_t*)((__half*)Cout + (size_t)row * N + col) = *(uint32_t*)&hv;
                    }
                    if (MODE == 2) {
                        v0 += bias[col]     + res[(size_t)row * N + col];
                        v1 += bias[col + 1] + res[(size_t)row * N + col + 1];
                        *(float2*)((float*)Cout + (size_t)row * N + col) = make_float2(v0, v1);
                    }
                }
            }
        }
    }
}

// ---------------------------------------------------------------------------
// fp16 flash attention, PERSISTENT CTAs, Q-tile 128 rows, no-max softmax,
// register-resident P. Work item = (bh, qt); order bh*8+qt keeps consecutive
// items on the same head's K/V (L2 reuse). grid = min(NSLOTS, 512).
// smem halves: Qs[128][72], Ks[2][64][72], Vs[2][64][72] = 55296 B
// ---------------------------------------------------------------------------
#define QP 72
__global__ __launch_bounds__(128, 2) void attn_h_kernel(
    const __half* __restrict__ QKV, const float* __restrict__ res,
    float* __restrict__ O)
{
    extern __shared__ __half sh[];
    __half* Qs = sh;                  // [128][QP]
    __half* Ks = sh + 128 * QP;       // [2][64][QP]
    __half* Vs = Ks + 2 * 64 * QP;    // [2][64][QP]

    const int tid  = threadIdx.x;
    const int warp = tid >> 5, lane = tid & 31;
    const int g = lane >> 2, tq = lane & 3;
    const int wrow = warp * 32;

    const uint32_t qb = (uint32_t)__cvta_generic_to_shared(Qs);
    const uint32_t kbase = (uint32_t)__cvta_generic_to_shared(Ks);
    const uint32_t vbase = (uint32_t)__cvta_generic_to_shared(Vs);

    for (int work = blockIdx.x; work < 512; work += gridDim.x) {
        const int qt = work & 7;
        const int bh = work >> 3, b = bh >> 4, h = bh & 15;

        const __half* Qg = QKV + ((size_t)(b * 1024 + qt * 128)) * 3072 + h * 64;
        const __half* Kg = QKV + (size_t)b * 1024 * 3072 + 1024 + h * 64;
        const __half* Vg = QKV + (size_t)b * 1024 * 3072 + 2048 + h * 64;

        auto stageKV = [&](int t) {
            const uint32_t kb0 = kbase + (uint32_t)((t & 1) * 64 * QP) * 2;
            const uint32_t vb0 = vbase + (uint32_t)((t & 1) * 64 * QP) * 2;
            #pragma unroll
            for (int i = 0; i < 4; i++) {
                int id = tid + (i << 7);
                int r = id >> 3, c = (id & 7) * 8;
                cp16(kb0 + (uint32_t)(r * QP + c) * 2, Kg + (size_t)(t * 64 + r) * 3072 + c);
            }
            #pragma unroll
            for (int i = 0; i < 4; i++) {
                int id = tid + (i << 7);
                int r = id >> 3, c = (id & 7) * 8;
                cp16(vb0 + (uint32_t)(r * QP + c) * 2, Vg + (size_t)(t * 64 + r) * 3072 + c);
            }
            CP_COMMIT();
        };

        __syncthreads();   // smem reuse guard across work items

        // stage Q (128 rows; group 0), then KV tile 0 (group 1)
        #pragma unroll
        for (int i = 0; i < 8; i++) {
            int id = tid + (i << 7);
            int r = id >> 3, c = (id & 7) * 8;
            cp16(qb + (uint32_t)(r * QP + c) * 2, Qg + (size_t)r * 3072 + c);
        }
        CP_COMMIT();
        stageKV(0);

        asm volatile("cp.async.wait_group 1;\n" ::: "memory");   // Q landed
        __syncthreads();
        uint32_t qf[2][4][4];
        #pragma unroll
        for (int mi = 0; mi < 2; mi++)
            #pragma unroll
            for (int ks = 0; ks < 4; ks++) {
                uint32_t addr = qb +
                    (uint32_t)((wrow + mi * 16 + (lane & 15)) * QP + ks * 16 + (lane >> 4) * 8) * 2;
                ldsm_x4(qf[mi][ks][0], qf[mi][ks][1], qf[mi][ks][2], qf[mi][ks][3], addr);
            }

        float l[2][2] = {};
        float oacc[2][8][4] = {};

        for (int st = 0; st < 16; st++) {
            if (st + 1 < 16) {
                stageKV(st + 1);
                asm volatile("cp.async.wait_group 1;\n" ::: "memory");
            } else {
                asm volatile("cp.async.wait_group 0;\n" ::: "memory");
            }
            __syncthreads();

            const uint32_t kb0 = kbase + (uint32_t)((st & 1) * 64 * QP) * 2;
            const uint32_t vb0 = vbase + (uint32_t)((st & 1) * 64 * QP) * 2;

            // S = Q K^T (m32 x n64, k64)
            float sacc[2][8][4] = {};
            #pragma unroll
            for (int ks = 0; ks < 4; ks++) {
                const int kb = ks * 16;
                uint32_t bf[8][2];
                #pragma unroll
                for (int nj = 0; nj < 4; nj++) {
                    uint32_t r0, r1, r2, r3;
                    uint32_t addr = kb0 +
                        (uint32_t)((nj * 16 + (lane & 15)) * QP + kb + (lane >> 4) * 8) * 2;
                    ldsm_x4(r0, r1, r2, r3, addr);
                    bf[nj * 2][0] = r0; bf[nj * 2][1] = r2;
                    bf[nj * 2 + 1][0] = r1; bf[nj * 2 + 1][1] = r3;
                }
                #pragma unroll
                for (int mi = 0; mi < 2; mi++)
                    #pragma unroll
                    for (int ni = 0; ni < 8; ni++)
                        mma_f16(sacc[mi][ni], qf[mi][ks][0], qf[mi][ks][1],
                                qf[mi][ks][2], qf[mi][ks][3], bf[ni][0], bf[ni][1]);
            }

            // no-max softmax: p = exp(s/32); pack P into PV A-fragments in regs.
            uint32_t ph[2][8][2];
            #pragma unroll
            for (int mi = 0; mi < 2; mi++) {
                #pragma unroll
                for (int ni = 0; ni < 8; ni++) {
                    float p0 = __expf(sacc[mi][ni][0] * 0.03125f);
                    float p1 = __expf(sacc[mi][ni][1] * 0.03125f);
                    float p2 = __expf(sacc[mi][ni][2] * 0.03125f);
                    float p3 = __expf(sacc[mi][ni][3] * 0.03125f);
                    l[mi][0] += p0 + p1;
                    l[mi][1] += p2 + p3;
                    __half2 hp0 = __floats2half2_rn(p0, p1);
                    __half2 hp1 = __floats2half2_rn(p2, p3);
                    ph[mi][ni][0] = *(uint32_t*)&hp0;
                    ph[mi][ni][1] = *(uint32_t*)&hp1;
                }
            }

            // O += P V (A-frags from registers)
            #pragma unroll
            for (int j = 0; j < 4; j++) {
                const int kb = j * 16;
                uint32_t bf[8][2];
                #pragma unroll
                for (int nj = 0; nj < 4; nj++) {
                    uint32_t addr = vb0 +
                        (uint32_t)((kb + (lane & 15)) * QP + nj * 16 + (lane >> 4) * 8) * 2;
                    ldsm_x4t(bf[nj * 2][0], bf[nj * 2][1],
                             bf[nj * 2 + 1][0], bf[nj * 2 + 1][1], addr);
                }
                #pragma unroll
                for (int mi = 0; mi < 2; mi++) {
                    #pragma unroll
                    for (int ni = 0; ni < 8; ni++)
                        mma_f16(oacc[mi][ni],
                                ph[mi][2 * j][0], ph[mi][2 * j][1],
                                ph[mi][2 * j + 1][0], ph[mi][2 * j + 1][1],
                                bf[ni][0], bf[ni][1]);
                }
            }
            __syncthreads();   // all warps done with this K/V buffer
        }

        // reduce row sums across the quad (tq axis)
        #pragma unroll
        for (int mi = 0; mi < 2; mi++)
            #pragma unroll
            for (int hf = 0; hf < 2; hf++) {
                #pragma unroll
                for (int off = 1; off < 4; off <<= 1)
                    l[mi][hf] += __shfl_xor_sync(0xffffffffu, l[mi][hf], off);
            }

        const size_t obase = ((size_t)(b * 1024 + qt * 128 + wrow)) * 1024 + h * 64;
        #pragma unroll
        for (int mi = 0; mi < 2; mi++) {
            const float inv0 = 1.f / l[mi][0], inv1 = 1.f / l[mi][1];
            #pragma unroll
            for (int ni = 0; ni < 8; ni++) {
                const int col = ni * 8 + 2 * tq;
                const size_t a0 = obase + (size_t)(mi * 16 + g) * 1024 + col;
                const size_t a1 = obase + (size_t)(mi * 16 + g + 8) * 1024 + col;
                float2 r0 = *(const float2*)(res + a0);
                float2 r1 = *(const float2*)(res + a1);
                *(float2*)(O + a0) = make_float2(oacc[mi][ni][0] * inv0 + r0.x,
                                                 oacc[mi][ni][1] * inv0 + r0.y);
                *(float2*)(O + a1) = make_float2(oacc[mi][ni][2] * inv1 + r1.x,
                                                 oacc[mi][ni][3] * inv1 + r1.y);
            }
        }
    }
}

// ---------------------------------------------------------------------------
// Host launch
// ---------------------------------------------------------------------------
static inline int gmin(int a, int b) { return a < b ? a : b; }

extern "C" void kernel_launch(void* const* d_in, const int* in_sizes, int n_in,
                              void* d_out, int out_size)
{
    (void)in_sizes; (void)n_in; (void)out_size;
    const float* x   = (const float*)d_in[0];
    const float* Wq1 = (const float*)d_in[1];
    const float* Wk1 = (const float*)d_in[2];
    const float* Wv1 = (const float*)d_in[3];
    const float* Wq2 = (const float*)d_in[4];
    const float* Wk2 = (const float*)d_in[5];
    const float* Wv2 = (const float*)d_in[6];
    const float* g1  = (const float*)d_in[7];
    const float* b1  = (const float*)d_in[8];
    const float* g2  = (const float*)d_in[9];
    const float* b2  = (const float*)d_in[10];
    const float* g3  = (const float*)d_in[11];
    const float* b3  = (const float*)d_in[12];
    const float* W1  = (const float*)d_in[13];
    const float* bf1 = (const float*)d_in[14];
    const float* W2  = (const float*)d_in[15];
    const float* bf2 = (const float*)d_in[16];
    float* out = (float*)d_out;

    __half *ln, *qkv, *h1, *wt, *w1, *w2;
    float *x1, *x2;
    cudaGetSymbolAddress((void**)&ln,  g_ln);
    cudaGetSymbolAddress((void**)&qkv, g_qkv);
    cudaGetSymbolAddress((void**)&x1,  g_x1);
    cudaGetSymbolAddress((void**)&x2,  g_x2);
    cudaGetSymbolAddress((void**)&h1,  g_h1);
    cudaGetSymbolAddress((void**)&wt,  g_wt);
    cudaGetSymbolAddress((void**)&w1,  g_w1);
    cudaGetSymbolAddress((void**)&w2,  g_w2);

    const int GEMM_SMEM = 4 * STG * 2;                 // 75776
    const int ATTN_SMEM = (128 + 256) * QP * 2;        // 55296
    cudaFuncSetAttribute(hgemm_kernel<0>, cudaFuncAttributeMaxDynamicSharedMemorySize, GEMM_SMEM);
    cudaFuncSetAttribute(hgemm_kernel<1>, cudaFuncAttributeMaxDynamicSharedMemorySize, GEMM_SMEM);
    cudaFuncSetAttribute(hgemm_kernel<2>, cudaFuncAttributeMaxDynamicSharedMemorySize, GEMM_SMEM);
    cudaFuncSetAttribute(attn_h_kernel,   cudaFuncAttributeMaxDynamicSharedMemorySize, ATTN_SMEM);

    const int M = TOK, C = CDIM;
    const size_t LSZ = (size_t)C * 3072;

    dim3 gW(4096, 6);
    wtrans6_kernel<<<gW, 256>>>(Wq1, Wk1, Wv1, Wq2, Wk2, Wv2, wt);
    wconv2_kernel<<<8192, 256>>>((const float4*)W1, (const float4*)W2, w1, w2);

    // persistent grids
    const int TQKV  = (3072 / 128) * (M / 128);   // 24*32 = 768
    const int TMLP1 = (HID / 128) * (M / 128);    // 32*32 = 1024
    const int TMLP2 = (C / 128) * (M / 128);      // 8*32  = 256
    const int gQKV  = gmin(NSLOTS, TQKV);
    const int gMLP1 = gmin(NSLOTS, TMLP1);
    const int gMLP2 = gmin(NSLOTS, TMLP2);
    const int gAttn = gmin(NSLOTS, 512);

    // --- MSA block 1 ---
    ln_kernel<<<TOK, 256>>>(x, g1, b1, ln);
    hgemm_kernel<0><<<gQKV, 128, GEMM_SMEM>>>(ln, wt + 0 * LSZ, nullptr, nullptr, qkv, M, 3072, C, 3072 / 128, TQKV);
    attn_h_kernel<<<gAttn, 128, ATTN_SMEM>>>(qkv, x, x1);      // x1 = x + msa1

    // --- MSA block 2 ---
    ln_kernel<<<TOK, 256>>>(x1, g2, b2, ln);
    hgemm_kernel<0><<<gQKV, 128, GEMM_SMEM>>>(ln, wt + 1 * LSZ, nullptr, nullptr, qkv, M, 3072, C, 3072 / 128, TQKV);
    attn_h_kernel<<<gAttn, 128, ATTN_SMEM>>>(qkv, x1, x2);     // x2 = x1 + msa2

    // --- MLP block ---
    ln_kernel<<<TOK, 256>>>(x2, g3, b3, ln);
    hgemm_kernel<1><<<gMLP1, 128, GEMM_SMEM>>>(ln, w1, bf1, nullptr, h1, M, HID, C, HID / 128, TMLP1);
    hgemm_kernel<2><<<gMLP2, 128, GEMM_SMEM>>>(h1, w2, bf2, x2, out, M, C, HID, C / 128, TMLP2);
}

// round 14
// speedup vs baseline: 1.0980x; 1.0980x over previous
#include <cuda_runtime.h>
#include <cuda_fp16.h>
#include <math.h>
#include <stdint.h>

// ---------------------------------------------------------------------------
// Scratch (device globals; no allocation allowed)
// ---------------------------------------------------------------------------
#define TOK 4096              // B*T = 4*1024
#define CDIM 1024
#define HID 4096

__device__ __half g_ln [TOK * CDIM];
__device__ __half g_qkv[TOK * 3072];
__device__ float  g_x1 [TOK * CDIM];
__device__ float  g_x2 [TOK * CDIM];
__device__ __half g_h1 [TOK * HID];
__device__ __half g_wt [2 * CDIM * 3072];   // per layer: [C=1024][3072] = Wq|Wk|Wv
__device__ __half g_w1 [CDIM * HID];
__device__ __half g_w2 [HID * CDIM];

// ---------------------------------------------------------------------------
// helpers
// ---------------------------------------------------------------------------
__device__ __forceinline__ void mma_f16(float c[4],
    uint32_t a0, uint32_t a1, uint32_t a2, uint32_t a3,
    uint32_t b0, uint32_t b1)
{
    asm volatile(
        "mma.sync.aligned.m16n8k16.row.col.f32.f16.f16.f32 "
        "{%0,%1,%2,%3}, {%4,%5,%6,%7}, {%8,%9}, {%0,%1,%2,%3};\n"
        : "+f"(c[0]), "+f"(c[1]), "+f"(c[2]), "+f"(c[3])
        : "r"(a0), "r"(a1), "r"(a2), "r"(a3), "r"(b0), "r"(b1));
}

__device__ __forceinline__ void ldsm_x4(uint32_t& r0, uint32_t& r1,
                                        uint32_t& r2, uint32_t& r3, uint32_t addr)
{
    asm volatile("ldmatrix.sync.aligned.m8n8.x4.shared.b16 {%0,%1,%2,%3}, [%4];"
        : "=r"(r0), "=r"(r1), "=r"(r2), "=r"(r3) : "r"(addr));
}
__device__ __forceinline__ void ldsm_x4t(uint32_t& r0, uint32_t& r1,
                                         uint32_t& r2, uint32_t& r3, uint32_t addr)
{
    asm volatile("ldmatrix.sync.aligned.m8n8.x4.trans.shared.b16 {%0,%1,%2,%3}, [%4];"
        : "=r"(r0), "=r"(r1), "=r"(r2), "=r"(r3) : "r"(addr));
}

__device__ __forceinline__ void cp16(uint32_t dst_smem, const void* src) {
    asm volatile("cp.async.cg.shared.global [%0], [%1], 16;\n"
        :: "r"(dst_smem), "l"(src));
}
#define CP_COMMIT() asm volatile("cp.async.commit_group;\n" ::: "memory")

// ---------------------------------------------------------------------------
// Fused weight transpose: six [H=16,C=1024,d=64] -> half cols of [C][3072]
// grid (4096, 6)
// ---------------------------------------------------------------------------
__global__ void wtrans6_kernel(
    const float* __restrict__ s0, const float* __restrict__ s1,
    const float* __restrict__ s2, const float* __restrict__ s3,
    const float* __restrict__ s4, const float* __restrict__ s5,
    __half* __restrict__ wt)
{
    const float* srcs[6] = {s0, s1, s2, s3, s4, s5};
    const int which = blockIdx.y;
    const float* W = srcs[which];
    __half* Wt = wt + (size_t)(which / 3) * (CDIM * 3072) + (which % 3) * 1024;
    int idx = blockIdx.x * 256 + threadIdx.x;       // 0 .. 1M-1
    int dd = idx & 63;
    int c  = (idx >> 6) & 1023;
    int h  = idx >> 16;
    Wt[(size_t)c * 3072 + h * 64 + dd] = __float2half(W[idx]);
}

// Convert W1 and W2 (4M floats each) to half. grid 8192 x 256, float4 each.
__global__ void wconv2_kernel(const float4* __restrict__ W1,
                              const float4* __restrict__ W2,
                              __half* __restrict__ w1, __half* __restrict__ w2)
{
    int i = blockIdx.x * 256 + threadIdx.x;         // 0 .. 2M-1
    const bool second = i >= (1 << 20);
    int j = second ? i - (1 << 20) : i;
    float4 v = second ? W2[j] : W1[j];
    __half2 h0 = __floats2half2_rn(v.x, v.y);
    __half2 h1 = __floats2half2_rn(v.z, v.w);
    uint2 u = make_uint2(*(uint32_t*)&h0, *(uint32_t*)&h1);
    if (second) ((uint2*)w2)[j] = u; else ((uint2*)w1)[j] = u;
}

// ---------------------------------------------------------------------------
// LayerNorm: one block per row of 1024; half output
// ---------------------------------------------------------------------------
__global__ __launch_bounds__(256) void ln_kernel(
    const float* __restrict__ x, const float* __restrict__ g,
    const float* __restrict__ b, __half* __restrict__ out)
{
    __shared__ float red[2][8];
    const int row = blockIdx.x;
    const int tid = threadIdx.x;
    const float4 xv = ((const float4*)(x + (size_t)row * 1024))[tid];
    float s  = xv.x + xv.y + xv.z + xv.w;
    float ss = xv.x*xv.x + xv.y*xv.y + xv.z*xv.z + xv.w*xv.w;
    #pragma unroll
    for (int off = 16; off; off >>= 1) {
        s  += __shfl_xor_sync(0xffffffffu, s,  off);
        ss += __shfl_xor_sync(0xffffffffu, ss, off);
    }
    const int warp = tid >> 5, lane = tid & 31;
    if (lane == 0) { red[0][warp] = s; red[1][warp] = ss; }
    __syncthreads();
    float st = 0.f, sst = 0.f;
    #pragma unroll
    for (int i = 0; i < 8; i++) { st += red[0][i]; sst += red[1][i]; }
    const float mean = st * (1.f / 1024.f);
    const float var  = sst * (1.f / 1024.f) - mean * mean;
    const float inv  = rsqrtf(var + 1e-5f);
    const float4 gv = ((const float4*)g)[tid];
    const float4 bv = ((const float4*)b)[tid];
    __half2 h0 = __floats2half2_rn((xv.x - mean) * inv * gv.x + bv.x,
                                   (xv.y - mean) * inv * gv.y + bv.y);
    __half2 h1 = __floats2half2_rn((xv.z - mean) * inv * gv.z + bv.z,
                                   (xv.w - mean) * inv * gv.w + bv.w);
    ((uint2*)(out + (size_t)row * 1024))[tid] =
        make_uint2(*(uint32_t*)&h0, *(uint32_t*)&h1);
}

// ---------------------------------------------------------------------------
// fp16 tensor-core GEMM, cp.async 4-stage, ldmatrix fragments.
//   C[M,N] = A[M,K] @ B[K,N]  (+ epilogue)
//   MODE 0: plain -> half out   MODE 1: +bias, relu -> half out
//   MODE 2: +bias +res -> float out
// CTA tile 128x128, BK=32, 128 thr = 4 warps (2Mx2N), warp tile 64x64.
// 2 CTAs/SM; 4-stage pipeline (3 tiles in flight). Prefetch for slab s+3 is
// issued BETWEEN the two k16 half-blocks: ks=0's MMAs cover the cp.async
// issue latency without delaying ks=0's fragment loads.
// smem (halves): 4 stages x (A[128][40] + B[32][136]) = 75776 B
// ---------------------------------------------------------------------------
#define AP   40
#define BP   136
#define ASTG (128 * AP)
#define BSTG (32 * BP)
#define STG  (ASTG + BSTG)
template<int MODE>
__global__ __launch_bounds__(128, 2) void hgemm_kernel(
    const __half* __restrict__ A, const __half* __restrict__ B,
    const float* __restrict__ bias, const float* __restrict__ res,
    void* __restrict__ Cout, int M, int N, int K)
{
    extern __shared__ __half sh[];
    const int tid  = threadIdx.x;
    const int warp = tid >> 5, lane = tid & 31;
    const int g  = lane >> 2, tq = lane & 3;
    const int wm = (warp >> 1) * 64;     // 0,64  (warp covers 64 M rows)
    const int wn = (warp & 1) * 64;      // 0,64

    const __half* Ag = A + (size_t)(blockIdx.y * 128) * K;
    const __half* Bg = B + blockIdx.x * 128;
    const uint32_t sb = (uint32_t)__cvta_generic_to_shared(sh);

    auto stage = [&](int s) {
        const int k0 = s * 32;
        const uint32_t ab = sb + (uint32_t)((s & 3) * STG) * 2;
        const uint32_t bb = ab + ASTG * 2;
        #pragma unroll
        for (int i = 0; i < 4; i++) {               // A: 128 rows x 4 chunks
            int id = tid + (i << 7);
            int r = id >> 2, c = (id & 3) * 8;
            cp16(ab + (uint32_t)(r * AP + c) * 2, Ag + (size_t)r * K + k0 + c);
        }
        #pragma unroll
        for (int i = 0; i < 4; i++) {               // B: 32 rows x 16 chunks
            int id = tid + (i << 7);
            int r = id >> 4, c = (id & 15) * 8;
            cp16(bb + (uint32_t)(r * BP + c) * 2, Bg + (size_t)(k0 + r) * N + c);
        }
        CP_COMMIT();
    };

    float acc[4][8][4] = {};
    stage(0); stage(1); stage(2);

    const int NS = K / 32;
    for (int s = 0; s < NS; s++) {
        if (s < NS - 2)       asm volatile("cp.async.wait_group 2;\n" ::: "memory");
        else if (s == NS - 2) asm volatile("cp.async.wait_group 1;\n" ::: "memory");
        else                  asm volatile("cp.async.wait_group 0;\n" ::: "memory");
        __syncthreads();

        const uint32_t ab = sb + (uint32_t)((s & 3) * STG) * 2;
        const uint32_t bb = ab + ASTG * 2;
        #pragma unroll
        for (int ks = 0; ks < 2; ks++) {
            const int kb = ks * 16;
            uint32_t af[4][4];
            #pragma unroll
            for (int mi = 0; mi < 4; mi++) {
                uint32_t addr = ab +
                    (uint32_t)((wm + mi * 16 + (lane & 15)) * AP + kb + (lane >> 4) * 8) * 2;
                ldsm_x4(af[mi][0], af[mi][1], af[mi][2], af[mi][3], addr);
            }
            uint32_t bf[8][2];
            #pragma unroll
            for (int nj = 0; nj < 4; nj++) {
                uint32_t addr = bb +
                    (uint32_t)((kb + (lane & 15)) * BP + wn + nj * 16 + (lane >> 4) * 8) * 2;
                ldsm_x4t(bf[nj * 2][0], bf[nj * 2][1],
                         bf[nj * 2 + 1][0], bf[nj * 2 + 1][1], addr);
            }
            #pragma unroll
            for (int mi = 0; mi < 4; mi++)
                #pragma unroll
                for (int ni = 0; ni < 8; ni++)
                    mma_f16(acc[mi][ni], af[mi][0], af[mi][1], af[mi][2], af[mi][3],
                            bf[ni][0], bf[ni][1]);
            if (ks == 0 && s + 3 < NS) stage(s + 3);   // prefetch mid-block
        }
    }

    #pragma unroll
    for (int mi = 0; mi < 4; mi++) {
        #pragma unroll
        for (int ni = 0; ni < 8; ni++) {
            const int row0 = blockIdx.y * 128 + wm + mi * 16 + g;
            const int col  = blockIdx.x * 128 + wn + ni * 8 + 2 * tq;
            #pragma unroll
            for (int half_i = 0; half_i < 2; half_i++) {
                const int row = row0 + half_i * 8;
                float v0 = acc[mi][ni][half_i * 2 + 0];
                float v1 = acc[mi][ni][half_i * 2 + 1];
                if (MODE == 0) {
                    __half2 hv = __floats2half2_rn(v0, v1);
                    *(uint32_t*)((__half*)Cout + (size_t)row * N + col) = *(uint32_t*)&hv;
                }
                if (MODE == 1) {
                    v0 = fmaxf(v0 + bias[col], 0.f);
                    v1 = fmaxf(v1 + bias[col + 1], 0.f);
                    __half2 hv = __floats2half2_rn(v0, v1);
                    *(uint32_t*)((__half*)Cout + (size_t)row * N + col) = *(uint32_t*)&hv;
                }
                if (MODE == 2) {
                    v0 += bias[col]     + res[(size_t)row * N + col];
                    v1 += bias[col + 1] + res[(size_t)row * N + col + 1];
                    *(float2*)((float*)Cout + (size_t)row * N + col) = make_float2(v0, v1);
                }
            }
        }
    }
}

// ---------------------------------------------------------------------------
// fp16 flash attention, Q-tile 128 rows, no-max softmax, REGISTER-RESIDENT P.
// (R11 winner, unchanged.)
// Block = 128 q rows, 4 warps x 32 rows (2 m16 tiles). d=64, T=1024.
// smem halves: Qs[128][72], Ks[2][64][72], Vs[2][64][72] = 55296 B
// ---------------------------------------------------------------------------
#define QP 72
__global__ __launch_bounds__(128, 2) void attn_h_kernel(
    const __half* __restrict__ QKV, const float* __restrict__ res,
    float* __restrict__ O)
{
    extern __shared__ __half sh[];
    __half* Qs = sh;                  // [128][QP]
    __half* Ks = sh + 128 * QP;       // [2][64][QP]
    __half* Vs = Ks + 2 * 64 * QP;    // [2][64][QP]

    const int tid  = threadIdx.x;
    const int warp = tid >> 5, lane = tid & 31;
    const int g = lane >> 2, tq = lane & 3;
    const int bh = blockIdx.y, b = bh >> 4, h = bh & 15;
    const int qt = blockIdx.x;        // 0..7
    const int wrow = warp * 32;

    const uint32_t qb = (uint32_t)__cvta_generic_to_shared(Qs);
    const uint32_t kbase = (uint32_t)__cvta_generic_to_shared(Ks);
    const uint32_t vbase = (uint32_t)__cvta_generic_to_shared(Vs);

    const __half* Qg = QKV + ((size_t)(b * 1024 + qt * 128)) * 3072 + h * 64;
    const __half* Kg = QKV + (size_t)b * 1024 * 3072 + 1024 + h * 64;
    const __half* Vg = QKV + (size_t)b * 1024 * 3072 + 2048 + h * 64;

    auto stageKV = [&](int t) {
        const uint32_t kb0 = kbase + (uint32_t)((t & 1) * 64 * QP) * 2;
        const uint32_t vb0 = vbase + (uint32_t)((t & 1) * 64 * QP) * 2;
        #pragma unroll
        for (int i = 0; i < 4; i++) {
            int id = tid + (i << 7);
            int r = id >> 3, c = (id & 7) * 8;
            cp16(kb0 + (uint32_t)(r * QP + c) * 2, Kg + (size_t)(t * 64 + r) * 3072 + c);
        }
        #pragma unroll
        for (int i = 0; i < 4; i++) {
            int id = tid + (i << 7);
            int r = id >> 3, c = (id & 7) * 8;
            cp16(vb0 + (uint32_t)(r * QP + c) * 2, Vg + (size_t)(t * 64 + r) * 3072 + c);
        }
        CP_COMMIT();
    };

    // stage Q (128 rows; group 0), then KV tile 0 (group 1)
    #pragma unroll
    for (int i = 0; i < 8; i++) {
        int id = tid + (i << 7);
        int r = id >> 3, c = (id & 7) * 8;
        cp16(qb + (uint32_t)(r * QP + c) * 2, Qg + (size_t)r * 3072 + c);
    }
    CP_COMMIT();
    stageKV(0);

    asm volatile("cp.async.wait_group 1;\n" ::: "memory");   // Q landed
    __syncthreads();
    uint32_t qf[2][4][4];
    #pragma unroll
    for (int mi = 0; mi < 2; mi++)
        #pragma unroll
        for (int ks = 0; ks < 4; ks++) {
            uint32_t addr = qb +
                (uint32_t)((wrow + mi * 16 + (lane & 15)) * QP + ks * 16 + (lane >> 4) * 8) * 2;
            ldsm_x4(qf[mi][ks][0], qf[mi][ks][1], qf[mi][ks][2], qf[mi][ks][3], addr);
        }

    float l[2][2] = {};
    float oacc[2][8][4] = {};

    for (int st = 0; st < 16; st++) {
        if (st + 1 < 16) {
            stageKV(st + 1);
            asm volatile("cp.async.wait_group 1;\n" ::: "memory");
        } else {
            asm volatile("cp.async.wait_group 0;\n" ::: "memory");
        }
        __syncthreads();

        const uint32_t kb0 = kbase + (uint32_t)((st & 1) * 64 * QP) * 2;
        const uint32_t vb0 = vbase + (uint32_t)((st & 1) * 64 * QP) * 2;

        // S = Q K^T (m32 x n64, k64)
        float sacc[2][8][4] = {};
        #pragma unroll
        for (int ks = 0; ks < 4; ks++) {
            const int kb = ks * 16;
            uint32_t bf[8][2];
            #pragma unroll
            for (int nj = 0; nj < 4; nj++) {
                uint32_t r0, r1, r2, r3;
                uint32_t addr = kb0 +
                    (uint32_t)((nj * 16 + (lane & 15)) * QP + kb + (lane >> 4) * 8) * 2;
                ldsm_x4(r0, r1, r2, r3, addr);
                bf[nj * 2][0] = r0; bf[nj * 2][1] = r2;
                bf[nj * 2 + 1][0] = r1; bf[nj * 2 + 1][1] = r3;
            }
            #pragma unroll
            for (int mi = 0; mi < 2; mi++)
                #pragma unroll
                for (int ni = 0; ni < 8; ni++)
                    mma_f16(sacc[mi][ni], qf[mi][ks][0], qf[mi][ks][1],
                            qf[mi][ks][2], qf[mi][ks][3], bf[ni][0], bf[ni][1]);
        }

        // no-max softmax: p = exp(s/32); pack P into PV A-fragments in regs.
        uint32_t ph[2][8][2];
        #pragma unroll
        for (int mi = 0; mi < 2; mi++) {
            #pragma unroll
            for (int ni = 0; ni < 8; ni++) {
                float p0 = __expf(sacc[mi][ni][0] * 0.03125f);
                float p1 = __expf(sacc[mi][ni][1] * 0.03125f);
                float p2 = __expf(sacc[mi][ni][2] * 0.03125f);
                float p3 = __expf(sacc[mi][ni][3] * 0.03125f);
                l[mi][0] += p0 + p1;
                l[mi][1] += p2 + p3;
                __half2 hp0 = __floats2half2_rn(p0, p1);
                __half2 hp1 = __floats2half2_rn(p2, p3);
                ph[mi][ni][0] = *(uint32_t*)&hp0;
                ph[mi][ni][1] = *(uint32_t*)&hp1;
            }
        }

        // O += P V (A-frags from registers)
        #pragma unroll
        for (int j = 0; j < 4; j++) {
            const int kb = j * 16;
            uint32_t bf[8][2];
            #pragma unroll
            for (int nj = 0; nj < 4; nj++) {
                uint32_t addr = vb0 +
                    (uint32_t)((kb + (lane & 15)) * QP + nj * 16 + (lane >> 4) * 8) * 2;
                ldsm_x4t(bf[nj * 2][0], bf[nj * 2][1],
                         bf[nj * 2 + 1][0], bf[nj * 2 + 1][1], addr);
            }
            #pragma unroll
            for (int mi = 0; mi < 2; mi++) {
                #pragma unroll
                for (int ni = 0; ni < 8; ni++)
                    mma_f16(oacc[mi][ni],
                            ph[mi][2 * j][0], ph[mi][2 * j][1],
                            ph[mi][2 * j + 1][0], ph[mi][2 * j + 1][1],
                            bf[ni][0], bf[ni][1]);
            }
        }
        __syncthreads();   // all warps done with this K/V buffer
    }

    // reduce row sums across the quad (tq axis)
    #pragma unroll
    for (int mi = 0; mi < 2; mi++)
        #pragma unroll
        for (int hf = 0; hf < 2; hf++) {
            #pragma unroll
            for (int off = 1; off < 4; off <<= 1)
                l[mi][hf] += __shfl_xor_sync(0xffffffffu, l[mi][hf], off);
        }

    const size_t obase = ((size_t)(b * 1024 + qt * 128 + wrow)) * 1024 + h * 64;
    #pragma unroll
    for (int mi = 0; mi < 2; mi++) {
        const float inv0 = 1.f / l[mi][0], inv1 = 1.f / l[mi][1];
        #pragma unroll
        for (int ni = 0; ni < 8; ni++) {
            const int col = ni * 8 + 2 * tq;
            const size_t a0 = obase + (size_t)(mi * 16 + g) * 1024 + col;
            const size_t a1 = obase + (size_t)(mi * 16 + g + 8) * 1024 + col;
            float2 r0 = *(const float2*)(res + a0);
            float2 r1 = *(const float2*)(res + a1);
            *(float2*)(O + a0) = make_float2(oacc[mi][ni][0] * inv0 + r0.x,
                                             oacc[mi][ni][1] * inv0 + r0.y);
            *(float2*)(O + a1) = make_float2(oacc[mi][ni][2] * inv1 + r1.x,
                                             oacc[mi][ni][3] * inv1 + r1.y);
        }
    }
}

// ---------------------------------------------------------------------------
// Host launch
// ---------------------------------------------------------------------------
extern "C" void kernel_launch(void* const* d_in, const int* in_sizes, int n_in,
                              void* d_out, int out_size)
{
    (void)in_sizes; (void)n_in; (void)out_size;
    const float* x   = (const float*)d_in[0];
    const float* Wq1 = (const float*)d_in[1];
    const float* Wk1 = (const float*)d_in[2];
    const float* Wv1 = (const float*)d_in[3];
    const float* Wq2 = (const float*)d_in[4];
    const float* Wk2 = (const float*)d_in[5];
    const float* Wv2 = (const float*)d_in[6];
    const float* g1  = (const float*)d_in[7];
    const float* b1  = (const float*)d_in[8];
    const float* g2  = (const float*)d_in[9];
    const float* b2  = (const float*)d_in[10];
    const float* g3  = (const float*)d_in[11];
    const float* b3  = (const float*)d_in[12];
    const float* W1  = (const float*)d_in[13];
    const float* bf1 = (const float*)d_in[14];
    const float* W2  = (const float*)d_in[15];
    const float* bf2 = (const float*)d_in[16];
    float* out = (float*)d_out;

    __half *ln, *qkv, *h1, *wt, *w1, *w2;
    float *x1, *x2;
    cudaGetSymbolAddress((void**)&ln,  g_ln);
    cudaGetSymbolAddress((void**)&qkv, g_qkv);
    cudaGetSymbolAddress((void**)&x1,  g_x1);
    cudaGetSymbolAddress((void**)&x2,  g_x2);
    cudaGetSymbolAddress((void**)&h1,  g_h1);
    cudaGetSymbolAddress((void**)&wt,  g_wt);
    cudaGetSymbolAddress((void**)&w1,  g_w1);
    cudaGetSymbolAddress((void**)&w2,  g_w2);

    const int GEMM_SMEM = 4 * STG * 2;                 // 75776
    const int ATTN_SMEM = (128 + 256) * QP * 2;        // 55296
    cudaFuncSetAttribute(hgemm_kernel<0>, cudaFuncAttributeMaxDynamicSharedMemorySize, GEMM_SMEM);
    cudaFuncSetAttribute(hgemm_kernel<1>, cudaFuncAttributeMaxDynamicSharedMemorySize, GEMM_SMEM);
    cudaFuncSetAttribute(hgemm_kernel<2>, cudaFuncAttributeMaxDynamicSharedMemorySize, GEMM_SMEM);
    cudaFuncSetAttribute(attn_h_kernel,   cudaFuncAttributeMaxDynamicSharedMemorySize, ATTN_SMEM);

    const int M = TOK, C = CDIM;
    const size_t LSZ = (size_t)C * 3072;

    dim3 gW(4096, 6);
    wtrans6_kernel<<<gW, 256>>>(Wq1, Wk1, Wv1, Wq2, Wk2, Wv2, wt);
    wconv2_kernel<<<8192, 256>>>((const float4*)W1, (const float4*)W2, w1, w2);

    dim3 gQKV(3072 / 128, M / 128);    // (24, 32)
    dim3 gMLP1(HID / 128, M / 128);    // (32, 32)
    dim3 gMLP2(C / 128, M / 128);      // (8, 32)
    dim3 gAttn(8, 64);                 // 8 q-tiles of 128 x (B*H)

    // --- MSA block 1 ---
    ln_kernel<<<TOK, 256>>>(x, g1, b1, ln);
    hgemm_kernel<0><<<gQKV, 128, GEMM_SMEM>>>(ln, wt + 0 * LSZ, nullptr, nullptr, qkv, M, 3072, C);
    attn_h_kernel<<<gAttn, 128, ATTN_SMEM>>>(qkv, x, x1);      // x1 = x + msa1

    // --- MSA block 2 ---
    ln_kernel<<<TOK, 256>>>(x1, g2, b2, ln);
    hgemm_kernel<0><<<gQKV, 128, GEMM_SMEM>>>(ln, wt + 1 * LSZ, nullptr, nullptr, qkv, M, 3072, C);
    attn_h_kernel<<<gAttn, 128, ATTN_SMEM>>>(qkv, x1, x2);     // x2 = x1 + msa2

    // --- MLP block ---
    ln_kernel<<<TOK, 256>>>(x2, g3, b3, ln);
    hgemm_kernel<1><<<gMLP1, 128, GEMM_SMEM>>>(ln, w1, bf1, nullptr, h1, M, HID, C);
    hgemm_kernel<2><<<gMLP2, 128, GEMM_SMEM>>>(h1, w2, bf2, x2, out, M, C, HID);
}

// round 15
// speedup vs baseline: 1.1602x; 1.0566x over previous
#include <cuda_runtime.h>
#include <cuda_fp16.h>
#include <math.h>
#include <stdint.h>

// ---------------------------------------------------------------------------
// Scratch (device globals; no allocation allowed)
// ---------------------------------------------------------------------------
#define TOK 4096              // B*T = 4*1024
#define CDIM 1024
#define HID 4096

__device__ __half g_ln [TOK * CDIM];
__device__ __half g_qkv[TOK * 3072];
__device__ float  g_x1 [TOK * CDIM];
__device__ float  g_x2 [TOK * CDIM];
__device__ __half g_h1 [TOK * HID];
__device__ __half g_wt [2 * CDIM * 3072];   // per layer: [C=1024][3072] = Wq|Wk|Wv
__device__ __half g_w1 [CDIM * HID];
__device__ __half g_w2 [HID * CDIM];

// ---------------------------------------------------------------------------
// helpers
// ---------------------------------------------------------------------------
__device__ __forceinline__ void mma_f16(float c[4],
    uint32_t a0, uint32_t a1, uint32_t a2, uint32_t a3,
    uint32_t b0, uint32_t b1)
{
    asm volatile(
        "mma.sync.aligned.m16n8k16.row.col.f32.f16.f16.f32 "
        "{%0,%1,%2,%3}, {%4,%5,%6,%7}, {%8,%9}, {%0,%1,%2,%3};\n"
        : "+f"(c[0]), "+f"(c[1]), "+f"(c[2]), "+f"(c[3])
        : "r"(a0), "r"(a1), "r"(a2), "r"(a3), "r"(b0), "r"(b1));
}

__device__ __forceinline__ void ldsm_x4(uint32_t& r0, uint32_t& r1,
                                        uint32_t& r2, uint32_t& r3, uint32_t addr)
{
    asm volatile("ldmatrix.sync.aligned.m8n8.x4.shared.b16 {%0,%1,%2,%3}, [%4];"
        : "=r"(r0), "=r"(r1), "=r"(r2), "=r"(r3) : "r"(addr));
}
__device__ __forceinline__ void ldsm_x4t(uint32_t& r0, uint32_t& r1,
                                         uint32_t& r2, uint32_t& r3, uint32_t addr)
{
    asm volatile("ldmatrix.sync.aligned.m8n8.x4.trans.shared.b16 {%0,%1,%2,%3}, [%4];"
        : "=r"(r0), "=r"(r1), "=r"(r2), "=r"(r3) : "r"(addr));
}

__device__ __forceinline__ void cp16(uint32_t dst_smem, const void* src) {
    asm volatile("cp.async.cg.shared.global [%0], [%1], 16;\n"
        :: "r"(dst_smem), "l"(src));
}
#define CP_COMMIT() asm volatile("cp.async.commit_group;\n" ::: "memory")

// ---------------------------------------------------------------------------
// Fused preprocessing: grid (4096, 8)
//   y<6 : per-head transpose [H=16,C=1024,d=64] -> half cols of [C][3072]
//   y=6 : W1 float4 -> half    y=7 : W2 float4 -> half
// ---------------------------------------------------------------------------
__global__ void wprep_kernel(
    const float* __restrict__ s0, const float* __restrict__ s1,
    const float* __restrict__ s2, const float* __restrict__ s3,
    const float* __restrict__ s4, const float* __restrict__ s5,
    __half* __restrict__ wt,
    const float4* __restrict__ W1, const float4* __restrict__ W2,
    __half* __restrict__ w1, __half* __restrict__ w2)
{
    const int which = blockIdx.y;
    if (which < 6) {
        const float* srcs[6] = {s0, s1, s2, s3, s4, s5};
        const float* W = srcs[which];
        __half* Wt = wt + (size_t)(which / 3) * (CDIM * 3072) + (which % 3) * 1024;
        int idx = blockIdx.x * 256 + threadIdx.x;       // 0 .. 1M-1
        int dd = idx & 63;
        int c  = (idx >> 6) & 1023;
        int h  = idx >> 16;
        Wt[(size_t)c * 3072 + h * 64 + dd] = __float2half(W[idx]);
    } else {
        int j = blockIdx.x * 256 + threadIdx.x;         // 0 .. 1M-1 (float4s)
        float4 v = (which == 6) ? W1[j] : W2[j];
        __half2 h0 = __floats2half2_rn(v.x, v.y);
        __half2 h1 = __floats2half2_rn(v.z, v.w);
        uint2 u = make_uint2(*(uint32_t*)&h0, *(uint32_t*)&h1);
        if (which == 6) ((uint2*)w1)[j] = u; else ((uint2*)w2)[j] = u;
    }
}

// ---------------------------------------------------------------------------
// LayerNorm: one block per row of 1024; half output
// ---------------------------------------------------------------------------
__global__ __launch_bounds__(256) void ln_kernel(
    const float* __restrict__ x, const float* __restrict__ g,
    const float* __restrict__ b, __half* __restrict__ out)
{
    __shared__ float red[2][8];
    const int row = blockIdx.x;
    const int tid = threadIdx.x;
    const float4 xv = ((const float4*)(x + (size_t)row * 1024))[tid];
    float s  = xv.x + xv.y + xv.z + xv.w;
    float ss = xv.x*xv.x + xv.y*xv.y + xv.z*xv.z + xv.w*xv.w;
    #pragma unroll
    for (int off = 16; off; off >>= 1) {
        s  += __shfl_xor_sync(0xffffffffu, s,  off);
        ss += __shfl_xor_sync(0xffffffffu, ss, off);
    }
    const int warp = tid >> 5, lane = tid & 31;
    if (lane == 0) { red[0][warp] = s; red[1][warp] = ss; }
    __syncthreads();
    float st = 0.f, sst = 0.f;
    #pragma unroll
    for (int i = 0; i < 8; i++) { st += red[0][i]; sst += red[1][i]; }
    const float mean = st * (1.f / 1024.f);
    const float var  = sst * (1.f / 1024.f) - mean * mean;
    const float inv  = rsqrtf(var + 1e-5f);
    const float4 gv = ((const float4*)g)[tid];
    const float4 bv = ((const float4*)b)[tid];
    __half2 h0 = __floats2half2_rn((xv.x - mean) * inv * gv.x + bv.x,
                                   (xv.y - mean) * inv * gv.y + bv.y);
    __half2 h1 = __floats2half2_rn((xv.z - mean) * inv * gv.z + bv.z,
                                   (xv.w - mean) * inv * gv.w + bv.w);
    ((uint2*)(out + (size_t)row * 1024))[tid] =
        make_uint2(*(uint32_t*)&h0, *(uint32_t*)&h1);
}

// ---------------------------------------------------------------------------
// fp16 tensor-core GEMM, cp.async 4-stage, ldmatrix fragments. (R11 winner,
// FROZEN — prefetch after compute block, no mainloop changes.)
//   C[M,N] = A[M,K] @ B[K,N]  (+ epilogue)
//   MODE 0: plain -> half out   MODE 1: +bias, relu -> half out
//   MODE 2: +bias +res -> float out
// CTA tile 128x128, BK=32, 128 thr = 4 warps (2Mx2N), warp tile 64x64.
// 2 CTAs/SM; 4-stage pipeline (3 tiles in flight).
// smem (halves): 4 stages x (A[128][40] + B[32][136]) = 75776 B
// ---------------------------------------------------------------------------
#define AP   40
#define BP   136
#define ASTG (128 * AP)
#define BSTG (32 * BP)
#define STG  (ASTG + BSTG)
template<int MODE>
__global__ __launch_bounds__(128, 2) void hgemm_kernel(
    const __half* __restrict__ A, const __half* __restrict__ B,
    const float* __restrict__ bias, const float* __restrict__ res,
    void* __restrict__ Cout, int M, int N, int K)
{
    extern __shared__ __half sh[];
    const int tid  = threadIdx.x;
    const int warp = tid >> 5, lane = tid & 31;
    const int g  = lane >> 2, tq = lane & 3;
    const int wm = (warp >> 1) * 64;     // 0,64  (warp covers 64 M rows)
    const int wn = (warp & 1) * 64;      // 0,64

    const __half* Ag = A + (size_t)(blockIdx.y * 128) * K;
    const __half* Bg = B + blockIdx.x * 128;
    const uint32_t sb = (uint32_t)__cvta_generic_to_shared(sh);

    auto stage = [&](int s) {
        const int k0 = s * 32;
        const uint32_t ab = sb + (uint32_t)((s & 3) * STG) * 2;
        const uint32_t bb = ab + ASTG * 2;
        #pragma unroll
        for (int i = 0; i < 4; i++) {               // A: 128 rows x 4 chunks
            int id = tid + (i << 7);
            int r = id >> 2, c = (id & 3) * 8;
            cp16(ab + (uint32_t)(r * AP + c) * 2, Ag + (size_t)r * K + k0 + c);
        }
        #pragma unroll
        for (int i = 0; i < 4; i++) {               // B: 32 rows x 16 chunks
            int id = tid + (i << 7);
            int r = id >> 4, c = (id & 15) * 8;
            cp16(bb + (uint32_t)(r * BP + c) * 2, Bg + (size_t)(k0 + r) * N + c);
        }
        CP_COMMIT();
    };

    float acc[4][8][4] = {};
    stage(0); stage(1); stage(2);

    const int NS = K / 32;
    for (int s = 0; s < NS; s++) {
        if (s < NS - 2)       asm volatile("cp.async.wait_group 2;\n" ::: "memory");
        else if (s == NS - 2) asm volatile("cp.async.wait_group 1;\n" ::: "memory");
        else                  asm volatile("cp.async.wait_group 0;\n" ::: "memory");
        __syncthreads();

        const uint32_t ab = sb + (uint32_t)((s & 3) * STG) * 2;
        const uint32_t bb = ab + ASTG * 2;
        #pragma unroll
        for (int ks = 0; ks < 2; ks++) {
            const int kb = ks * 16;
            uint32_t af[4][4];
            #pragma unroll
            for (int mi = 0; mi < 4; mi++) {
                uint32_t addr = ab +
                    (uint32_t)((wm + mi * 16 + (lane & 15)) * AP + kb + (lane >> 4) * 8) * 2;
                ldsm_x4(af[mi][0], af[mi][1], af[mi][2], af[mi][3], addr);
            }
            uint32_t bf[8][2];
            #pragma unroll
            for (int nj = 0; nj < 4; nj++) {
                uint32_t addr = bb +
                    (uint32_t)((kb + (lane & 15)) * BP + wn + nj * 16 + (lane >> 4) * 8) * 2;
                ldsm_x4t(bf[nj * 2][0], bf[nj * 2][1],
                         bf[nj * 2 + 1][0], bf[nj * 2 + 1][1], addr);
            }
            #pragma unroll
            for (int mi = 0; mi < 4; mi++)
                #pragma unroll
                for (int ni = 0; ni < 8; ni++)
                    mma_f16(acc[mi][ni], af[mi][0], af[mi][1], af[mi][2], af[mi][3],
                            bf[ni][0], bf[ni][1]);
        }
        if (s + 3 < NS) stage(s + 3);
    }

    #pragma unroll
    for (int mi = 0; mi < 4; mi++) {
        #pragma unroll
        for (int ni = 0; ni < 8; ni++) {
            const int row0 = blockIdx.y * 128 + wm + mi * 16 + g;
            const int col  = blockIdx.x * 128 + wn + ni * 8 + 2 * tq;
            #pragma unroll
            for (int half_i = 0; half_i < 2; half_i++) {
                const int row = row0 + half_i * 8;
                float v0 = acc[mi][ni][half_i * 2 + 0];
                float v1 = acc[mi][ni][half_i * 2 + 1];
                if (MODE == 0) {
                    __half2 hv = __floats2half2_rn(v0, v1);
                    *(uint32_t*)((__half*)Cout + (size_t)row * N + col) = *(uint32_t*)&hv;
                }
                if (MODE == 1) {
                    v0 = fmaxf(v0 + bias[col], 0.f);
                    v1 = fmaxf(v1 + bias[col + 1], 0.f);
                    __half2 hv = __floats2half2_rn(v0, v1);
                    *(uint32_t*)((__half*)Cout + (size_t)row * N + col) = *(uint32_t*)&hv;
                }
                if (MODE == 2) {
                    v0 += bias[col]     + res[(size_t)row * N + col];
                    v1 += bias[col + 1] + res[(size_t)row * N + col + 1];
                    *(float2*)((float*)Cout + (size_t)row * N + col) = make_float2(v0, v1);
                }
            }
        }
    }
}

// ---------------------------------------------------------------------------
// fp16 flash attention, Q-tile 128 rows, no-max softmax, register-resident P,
// KV TRIPLE-BUFFERED: buffer (st+2)%3 written at top of iteration st+1 was
// last read in iteration st-1, and every warp passed the top-of-st barrier
// only after finishing st-1 — so the end-of-tile __syncthreads is removed.
// Block = 128 q rows, 4 warps x 32 rows (2 m16 tiles). d=64, T=1024.
// smem halves: Qs[128][72], Ks[3][64][72], Vs[3][64][72] = 73728 B (2 CTAs/SM)
// ---------------------------------------------------------------------------
#define QP 72
__global__ __launch_bounds__(128, 2) void attn_h_kernel(
    const __half* __restrict__ QKV, const float* __restrict__ res,
    float* __restrict__ O)
{
    extern __shared__ __half sh[];
    __half* Qs = sh;                  // [128][QP]
    __half* Ks = sh + 128 * QP;       // [3][64][QP]
    __half* Vs = Ks + 3 * 64 * QP;    // [3][64][QP]

    const int tid  = threadIdx.x;
    const int warp = tid >> 5, lane = tid & 31;
    const int g = lane >> 2, tq = lane & 3;
    const int bh = blockIdx.y, b = bh >> 4, h = bh & 15;
    const int qt = blockIdx.x;        // 0..7
    const int wrow = warp * 32;

    const uint32_t qb = (uint32_t)__cvta_generic_to_shared(Qs);
    const uint32_t kbase = (uint32_t)__cvta_generic_to_shared(Ks);
    const uint32_t vbase = (uint32_t)__cvta_generic_to_shared(Vs);

    const __half* Qg = QKV + ((size_t)(b * 1024 + qt * 128)) * 3072 + h * 64;
    const __half* Kg = QKV + (size_t)b * 1024 * 3072 + 1024 + h * 64;
    const __half* Vg = QKV + (size_t)b * 1024 * 3072 + 2048 + h * 64;

    auto stageKV = [&](int t) {
        const int buf = t % 3;
        const uint32_t kb0 = kbase + (uint32_t)(buf * 64 * QP) * 2;
        const uint32_t vb0 = vbase + (uint32_t)(buf * 64 * QP) * 2;
        #pragma unroll
        for (int i = 0; i < 4; i++) {
            int id = tid + (i << 7);
            int r = id >> 3, c = (id & 7) * 8;
            cp16(kb0 + (uint32_t)(r * QP + c) * 2, Kg + (size_t)(t * 64 + r) * 3072 + c);
        }
        #pragma unroll
        for (int i = 0; i < 4; i++) {
            int id = tid + (i << 7);
            int r = id >> 3, c = (id & 7) * 8;
            cp16(vb0 + (uint32_t)(r * QP + c) * 2, Vg + (size_t)(t * 64 + r) * 3072 + c);
        }
        CP_COMMIT();
    };

    // stage Q (128 rows; group 0), then KV tile 0 (group 1)
    #pragma unroll
    for (int i = 0; i < 8; i++) {
        int id = tid + (i << 7);
        int r = id >> 3, c = (id & 7) * 8;
        cp16(qb + (uint32_t)(r * QP + c) * 2, Qg + (size_t)r * 3072 + c);
    }
    CP_COMMIT();
    stageKV(0);

    asm volatile("cp.async.wait_group 1;\n" ::: "memory");   // Q landed
    __syncthreads();
    uint32_t qf[2][4][4];
    #pragma unroll
    for (int mi = 0; mi < 2; mi++)
        #pragma unroll
        for (int ks = 0; ks < 4; ks++) {
            uint32_t addr = qb +
                (uint32_t)((wrow + mi * 16 + (lane & 15)) * QP + ks * 16 + (lane >> 4) * 8) * 2;
            ldsm_x4(qf[mi][ks][0], qf[mi][ks][1], qf[mi][ks][2], qf[mi][ks][3], addr);
        }

    float l[2][2] = {};
    float oacc[2][8][4] = {};

    for (int st = 0; st < 16; st++) {
        if (st + 1 < 16) {
            stageKV(st + 1);
            asm volatile("cp.async.wait_group 1;\n" ::: "memory");
        } else {
            asm volatile("cp.async.wait_group 0;\n" ::: "memory");
        }
        __syncthreads();   // buffer st visible to all warps

        const int buf = st % 3;
        const uint32_t kb0 = kbase + (uint32_t)(buf * 64 * QP) * 2;
        const uint32_t vb0 = vbase + (uint32_t)(buf * 64 * QP) * 2;

        // S = Q K^T (m32 x n64, k64)
        float sacc[2][8][4] = {};
        #pragma unroll
        for (int ks = 0; ks < 4; ks++) {
            const int kb = ks * 16;
            uint32_t bf[8][2];
            #pragma unroll
            for (int nj = 0; nj < 4; nj++) {
                uint32_t r0, r1, r2, r3;
                uint32_t addr = kb0 +
                    (uint32_t)((nj * 16 + (lane & 15)) * QP + kb + (lane >> 4) * 8) * 2;
                ldsm_x4(r0, r1, r2, r3, addr);
                bf[nj * 2][0] = r0; bf[nj * 2][1] = r2;
                bf[nj * 2 + 1][0] = r1; bf[nj * 2 + 1][1] = r3;
            }
            #pragma unroll
            for (int mi = 0; mi < 2; mi++)
                #pragma unroll
                for (int ni = 0; ni < 8; ni++)
                    mma_f16(sacc[mi][ni], qf[mi][ks][0], qf[mi][ks][1],
                            qf[mi][ks][2], qf[mi][ks][3], bf[ni][0], bf[ni][1]);
        }

        // no-max softmax: p = exp(s/32); pack P into PV A-fragments in regs.
        uint32_t ph[2][8][2];
        #pragma unroll
        for (int mi = 0; mi < 2; mi++) {
            #pragma unroll
            for (int ni = 0; ni < 8; ni++) {
                float p0 = __expf(sacc[mi][ni][0] * 0.03125f);
                float p1 = __expf(sacc[mi][ni][1] * 0.03125f);
                float p2 = __expf(sacc[mi][ni][2] * 0.03125f);
                float p3 = __expf(sacc[mi][ni][3] * 0.03125f);
                l[mi][0] += p0 + p1;
                l[mi][1] += p2 + p3;
                __half2 hp0 = __floats2half2_rn(p0, p1);
                __half2 hp1 = __floats2half2_rn(p2, p3);
                ph[mi][ni][0] = *(uint32_t*)&hp0;
                ph[mi][ni][1] = *(uint32_t*)&hp1;
            }
        }

        // O += P V (A-frags from registers)
        #pragma unroll
        for (int j = 0; j < 4; j++) {
            const int kb = j * 16;
            uint32_t bf[8][2];
            #pragma unroll
            for (int nj = 0; nj < 4; nj++) {
                uint32_t addr = vb0 +
                    (uint32_t)((kb + (lane & 15)) * QP + nj * 16 + (lane >> 4) * 8) * 2;
                ldsm_x4t(bf[nj * 2][0], bf[nj * 2][1],
                         bf[nj * 2 + 1][0], bf[nj * 2 + 1][1], addr);
            }
            #pragma unroll
            for (int mi = 0; mi < 2; mi++) {
                #pragma unroll
                for (int ni = 0; ni < 8; ni++)
                    mma_f16(oacc[mi][ni],
                            ph[mi][2 * j][0], ph[mi][2 * j][1],
                            ph[mi][2 * j + 1][0], ph[mi][2 * j + 1][1],
                            bf[ni][0], bf[ni][1]);
            }
        }
        // no end-of-tile barrier: triple buffer guarantees reuse distance
    }

    // reduce row sums across the quad (tq axis)
    #pragma unroll
    for (int mi = 0; mi < 2; mi++)
        #pragma unroll
        for (int hf = 0; hf < 2; hf++) {
            #pragma unroll
            for (int off = 1; off < 4; off <<= 1)
                l[mi][hf] += __shfl_xor_sync(0xffffffffu, l[mi][hf], off);
        }

    const size_t obase = ((size_t)(b * 1024 + qt * 128 + wrow)) * 1024 + h * 64;
    #pragma unroll
    for (int mi = 0; mi < 2; mi++) {
        const float inv0 = 1.f / l[mi][0], inv1 = 1.f / l[mi][1];
        #pragma unroll
        for (int ni = 0; ni < 8; ni++) {
            const int col = ni * 8 + 2 * tq;
            const size_t a0 = obase + (size_t)(mi * 16 + g) * 1024 + col;
            const size_t a1 = obase + (size_t)(mi * 16 + g + 8) * 1024 + col;
            float2 r0 = *(const float2*)(res + a0);
            float2 r1 = *(const float2*)(res + a1);
            *(float2*)(O + a0) = make_float2(oacc[mi][ni][0] * inv0 + r0.x,
                                             oacc[mi][ni][1] * inv0 + r0.y);
            *(float2*)(O + a1) = make_float2(oacc[mi][ni][2] * inv1 + r1.x,
                                             oacc[mi][ni][3] * inv1 + r1.y);
        }
    }
}

// ---------------------------------------------------------------------------
// Host launch
// ---------------------------------------------------------------------------
extern "C" void kernel_launch(void* const* d_in, const int* in_sizes, int n_in,
                              void* d_out, int out_size)
{
    (void)in_sizes; (void)n_in; (void)out_size;
    const float* x   = (const float*)d_in[0];
    const float* Wq1 = (const float*)d_in[1];
    const float* Wk1 = (const float*)d_in[2];
    const float* Wv1 = (const float*)d_in[3];
    const float* Wq2 = (const float*)d_in[4];
    const float* Wk2 = (const float*)d_in[5];
    const float* Wv2 = (const float*)d_in[6];
    const float* g1  = (const float*)d_in[7];
    const float* b1  = (const float*)d_in[8];
    const float* g2  = (const float*)d_in[9];
    const float* b2  = (const float*)d_in[10];
    const float* g3  = (const float*)d_in[11];
    const float* b3  = (const float*)d_in[12];
    const float* W1  = (const float*)d_in[13];
    const float* bf1 = (const float*)d_in[14];
    const float* W2  = (const float*)d_in[15];
    const float* bf2 = (const float*)d_in[16];
    float* out = (float*)d_out;

    __half *ln, *qkv, *h1, *wt, *w1, *w2;
    float *x1, *x2;
    cudaGetSymbolAddress((void**)&ln,  g_ln);
    cudaGetSymbolAddress((void**)&qkv, g_qkv);
    cudaGetSymbolAddress((void**)&x1,  g_x1);
    cudaGetSymbolAddress((void**)&x2,  g_x2);
    cudaGetSymbolAddress((void**)&h1,  g_h1);
    cudaGetSymbolAddress((void**)&wt,  g_wt);
    cudaGetSymbolAddress((void**)&w1,  g_w1);
    cudaGetSymbolAddress((void**)&w2,  g_w2);

    const int GEMM_SMEM = 4 * STG * 2;                 // 75776
    const int ATTN_SMEM = (128 + 6 * 64) * QP * 2;     // 73728
    cudaFuncSetAttribute(hgemm_kernel<0>, cudaFuncAttributeMaxDynamicSharedMemorySize, GEMM_SMEM);
    cudaFuncSetAttribute(hgemm_kernel<1>, cudaFuncAttributeMaxDynamicSharedMemorySize, GEMM_SMEM);
    cudaFuncSetAttribute(hgemm_kernel<2>, cudaFuncAttributeMaxDynamicSharedMemorySize, GEMM_SMEM);
    cudaFuncSetAttribute(attn_h_kernel,   cudaFuncAttributeMaxDynamicSharedMemorySize, ATTN_SMEM);

    const int M = TOK, C = CDIM;
    const size_t LSZ = (size_t)C * 3072;

    dim3 gW(4096, 8);
    wprep_kernel<<<gW, 256>>>(Wq1, Wk1, Wv1, Wq2, Wk2, Wv2, wt,
                              (const float4*)W1, (const float4*)W2, w1, w2);

    dim3 gQKV(3072 / 128, M / 128);    // (24, 32)
    dim3 gMLP1(HID / 128, M / 128);    // (32, 32)
    dim3 gMLP2(C / 128, M / 128);      // (8, 32)
    dim3 gAttn(8, 64);                 // 8 q-tiles of 128 x (B*H)

    // --- MSA block 1 ---
    ln_kernel<<<TOK, 256>>>(x, g1, b1, ln);
    hgemm_kernel<0><<<gQKV, 128, GEMM_SMEM>>>(ln, wt + 0 * LSZ, nullptr, nullptr, qkv, M, 3072, C);
    attn_h_kernel<<<gAttn, 128, ATTN_SMEM>>>(qkv, x, x1);      // x1 = x + msa1

    // --- MSA block 2 ---
    ln_kernel<<<TOK, 256>>>(x1, g2, b2, ln);
    hgemm_kernel<0><<<gQKV, 128, GEMM_SMEM>>>(ln, wt + 1 * LSZ, nullptr, nullptr, qkv, M, 3072, C);
    attn_h_kernel<<<gAttn, 128, ATTN_SMEM>>>(qkv, x1, x2);     // x2 = x1 + msa2

    // --- MLP block ---
    ln_kernel<<<TOK, 256>>>(x2, g3, b3, ln);
    hgemm_kernel<1><<<gMLP1, 128, GEMM_SMEM>>>(ln, w1, bf1, nullptr, h1, M, HID, C);
    hgemm_kernel<2><<<gMLP2, 128, GEMM_SMEM>>>(h1, w2, bf2, x2, out, M, C, HID);
}

// round 16
// speedup vs baseline: 1.1695x; 1.0080x over previous
#include <cuda_runtime.h>
#include <cuda_fp16.h>
#include <math.h>
#include <stdint.h>

// ---------------------------------------------------------------------------
// Scratch (device globals; no allocation allowed)
// ---------------------------------------------------------------------------
#define TOK 4096              // B*T = 4*1024
#define CDIM 1024
#define HID 4096

__device__ __half g_ln [TOK * CDIM];
__device__ __half g_qkv[TOK * 3072];
__device__ float  g_x1 [TOK * CDIM];
__device__ float  g_x2 [TOK * CDIM];
__device__ __half g_h1 [TOK * HID];
__device__ __half g_wt [2 * CDIM * 3072];   // per layer: [C=1024][3072] = Wq|Wk|Wv
__device__ __half g_w1 [CDIM * HID];
__device__ __half g_w2 [HID * CDIM];

// ---------------------------------------------------------------------------
// helpers
// ---------------------------------------------------------------------------
__device__ __forceinline__ void mma_f16(float c[4],
    uint32_t a0, uint32_t a1, uint32_t a2, uint32_t a3,
    uint32_t b0, uint32_t b1)
{
    asm volatile(
        "mma.sync.aligned.m16n8k16.row.col.f32.f16.f16.f32 "
        "{%0,%1,%2,%3}, {%4,%5,%6,%7}, {%8,%9}, {%0,%1,%2,%3};\n"
        : "+f"(c[0]), "+f"(c[1]), "+f"(c[2]), "+f"(c[3])
        : "r"(a0), "r"(a1), "r"(a2), "r"(a3), "r"(b0), "r"(b1));
}

__device__ __forceinline__ void ldsm_x4(uint32_t& r0, uint32_t& r1,
                                        uint32_t& r2, uint32_t& r3, uint32_t addr)
{
    asm volatile("ldmatrix.sync.aligned.m8n8.x4.shared.b16 {%0,%1,%2,%3}, [%4];"
        : "=r"(r0), "=r"(r1), "=r"(r2), "=r"(r3) : "r"(addr));
}
__device__ __forceinline__ void ldsm_x4t(uint32_t& r0, uint32_t& r1,
                                         uint32_t& r2, uint32_t& r3, uint32_t addr)
{
    asm volatile("ldmatrix.sync.aligned.m8n8.x4.trans.shared.b16 {%0,%1,%2,%3}, [%4];"
        : "=r"(r0), "=r"(r1), "=r"(r2), "=r"(r3) : "r"(addr));
}

__device__ __forceinline__ void cp16(uint32_t dst_smem, const void* src) {
    asm volatile("cp.async.cg.shared.global [%0], [%1], 16;\n"
        :: "r"(dst_smem), "l"(src));
}
#define CP_COMMIT() asm volatile("cp.async.commit_group;\n" ::: "memory")

// raw ex2.approx — exp(s/32) == ex2(s * log2(e)/32), single FMUL-imm + MUFU
__device__ __forceinline__ float ex2f(float x) {
    float y;
    asm("ex2.approx.f32 %0, %1;" : "=f"(y) : "f"(x));
    return y;
}
#define EXP_SCALE 0.04508422f   // log2(e) / 32

// ---------------------------------------------------------------------------
// Fused preprocessing: grid (4096, 8)
//   y<6 : per-head transpose [H=16,C=1024,d=64] -> half cols of [C][3072]
//   y=6 : W1 float4 -> half    y=7 : W2 float4 -> half
// ---------------------------------------------------------------------------
__global__ void wprep_kernel(
    const float* __restrict__ s0, const float* __restrict__ s1,
    const float* __restrict__ s2, const float* __restrict__ s3,
    const float* __restrict__ s4, const float* __restrict__ s5,
    __half* __restrict__ wt,
    const float4* __restrict__ W1, const float4* __restrict__ W2,
    __half* __restrict__ w1, __half* __restrict__ w2)
{
    const int which = blockIdx.y;
    if (which < 6) {
        const float* srcs[6] = {s0, s1, s2, s3, s4, s5};
        const float* W = srcs[which];
        __half* Wt = wt + (size_t)(which / 3) * (CDIM * 3072) + (which % 3) * 1024;
        int idx = blockIdx.x * 256 + threadIdx.x;       // 0 .. 1M-1
        int dd = idx & 63;
        int c  = (idx >> 6) & 1023;
        int h  = idx >> 16;
        Wt[(size_t)c * 3072 + h * 64 + dd] = __float2half(W[idx]);
    } else {
        int j = blockIdx.x * 256 + threadIdx.x;         // 0 .. 1M-1 (float4s)
        float4 v = (which == 6) ? W1[j] : W2[j];
        __half2 h0 = __floats2half2_rn(v.x, v.y);
        __half2 h1 = __floats2half2_rn(v.z, v.w);
        uint2 u = make_uint2(*(uint32_t*)&h0, *(uint32_t*)&h1);
        if (which == 6) ((uint2*)w1)[j] = u; else ((uint2*)w2)[j] = u;
    }
}

// ---------------------------------------------------------------------------
// LayerNorm: one block per row of 1024; half output
// ---------------------------------------------------------------------------
__global__ __launch_bounds__(256) void ln_kernel(
    const float* __restrict__ x, const float* __restrict__ g,
    const float* __restrict__ b, __half* __restrict__ out)
{
    __shared__ float red[2][8];
    const int row = blockIdx.x;
    const int tid = threadIdx.x;
    const float4 xv = ((const float4*)(x + (size_t)row * 1024))[tid];
    float s  = xv.x + xv.y + xv.z + xv.w;
    float ss = xv.x*xv.x + xv.y*xv.y + xv.z*xv.z + xv.w*xv.w;
    #pragma unroll
    for (int off = 16; off; off >>= 1) {
        s  += __shfl_xor_sync(0xffffffffu, s,  off);
        ss += __shfl_xor_sync(0xffffffffu, ss, off);
    }
    const int warp = tid >> 5, lane = tid & 31;
    if (lane == 0) { red[0][warp] = s; red[1][warp] = ss; }
    __syncthreads();
    float st = 0.f, sst = 0.f;
    #pragma unroll
    for (int i = 0; i < 8; i++) { st += red[0][i]; sst += red[1][i]; }
    const float mean = st * (1.f / 1024.f);
    const float var  = sst * (1.f / 1024.f) - mean * mean;
    const float inv  = rsqrtf(var + 1e-5f);
    const float4 gv = ((const float4*)g)[tid];
    const float4 bv = ((const float4*)b)[tid];
    __half2 h0 = __floats2half2_rn((xv.x - mean) * inv * gv.x + bv.x,
                                   (xv.y - mean) * inv * gv.y + bv.y);
    __half2 h1 = __floats2half2_rn((xv.z - mean) * inv * gv.z + bv.z,
                                   (xv.w - mean) * inv * gv.w + bv.w);
    ((uint2*)(out + (size_t)row * 1024))[tid] =
        make_uint2(*(uint32_t*)&h0, *(uint32_t*)&h1);
}

// ---------------------------------------------------------------------------
// fp16 tensor-core GEMM, cp.async 4-stage, ldmatrix fragments. (R11 winner,
// FROZEN — prefetch after compute block, no mainloop changes.)
//   C[M,N] = A[M,K] @ B[K,N]  (+ epilogue)
//   MODE 0: plain -> half out   MODE 1: +bias, relu -> half out
//   MODE 2: +bias +res -> float out
// CTA tile 128x128, BK=32, 128 thr = 4 warps (2Mx2N), warp tile 64x64.
// 2 CTAs/SM; 4-stage pipeline (3 tiles in flight).
// smem (halves): 4 stages x (A[128][40] + B[32][136]) = 75776 B
// ---------------------------------------------------------------------------
#define AP   40
#define BP   136
#define ASTG (128 * AP)
#define BSTG (32 * BP)
#define STG  (ASTG + BSTG)
template<int MODE>
__global__ __launch_bounds__(128, 2) void hgemm_kernel(
    const __half* __restrict__ A, const __half* __restrict__ B,
    const float* __restrict__ bias, const float* __restrict__ res,
    void* __restrict__ Cout, int M, int N, int K)
{
    extern __shared__ __half sh[];
    const int tid  = threadIdx.x;
    const int warp = tid >> 5, lane = tid & 31;
    const int g  = lane >> 2, tq = lane & 3;
    const int wm = (warp >> 1) * 64;     // 0,64  (warp covers 64 M rows)
    const int wn = (warp & 1) * 64;      // 0,64

    const __half* Ag = A + (size_t)(blockIdx.y * 128) * K;
    const __half* Bg = B + blockIdx.x * 128;
    const uint32_t sb = (uint32_t)__cvta_generic_to_shared(sh);

    auto stage = [&](int s) {
        const int k0 = s * 32;
        const uint32_t ab = sb + (uint32_t)((s & 3) * STG) * 2;
        const uint32_t bb = ab + ASTG * 2;
        #pragma unroll
        for (int i = 0; i < 4; i++) {               // A: 128 rows x 4 chunks
            int id = tid + (i << 7);
            int r = id >> 2, c = (id & 3) * 8;
            cp16(ab + (uint32_t)(r * AP + c) * 2, Ag + (size_t)r * K + k0 + c);
        }
        #pragma unroll
        for (int i = 0; i < 4; i++) {               // B: 32 rows x 16 chunks
            int id = tid + (i << 7);
            int r = id >> 4, c = (id & 15) * 8;
            cp16(bb + (uint32_t)(r * BP + c) * 2, Bg + (size_t)(k0 + r) * N + c);
        }
        CP_COMMIT();
    };

    float acc[4][8][4] = {};
    stage(0); stage(1); stage(2);

    const int NS = K / 32;
    for (int s = 0; s < NS; s++) {
        if (s < NS - 2)       asm volatile("cp.async.wait_group 2;\n" ::: "memory");
        else if (s == NS - 2) asm volatile("cp.async.wait_group 1;\n" ::: "memory");
        else                  asm volatile("cp.async.wait_group 0;\n" ::: "memory");
        __syncthreads();

        const uint32_t ab = sb + (uint32_t)((s & 3) * STG) * 2;
        const uint32_t bb = ab + ASTG * 2;
        #pragma unroll
        for (int ks = 0; ks < 2; ks++) {
            const int kb = ks * 16;
            uint32_t af[4][4];
            #pragma unroll
            for (int mi = 0; mi < 4; mi++) {
                uint32_t addr = ab +
                    (uint32_t)((wm + mi * 16 + (lane & 15)) * AP + kb + (lane >> 4) * 8) * 2;
                ldsm_x4(af[mi][0], af[mi][1], af[mi][2], af[mi][3], addr);
            }
            uint32_t bf[8][2];
            #pragma unroll
            for (int nj = 0; nj < 4; nj++) {
                uint32_t addr = bb +
                    (uint32_t)((kb + (lane & 15)) * BP + wn + nj * 16 + (lane >> 4) * 8) * 2;
                ldsm_x4t(bf[nj * 2][0], bf[nj * 2][1],
                         bf[nj * 2 + 1][0], bf[nj * 2 + 1][1], addr);
            }
            #pragma unroll
            for (int mi = 0; mi < 4; mi++)
                #pragma unroll
                for (int ni = 0; ni < 8; ni++)
                    mma_f16(acc[mi][ni], af[mi][0], af[mi][1], af[mi][2], af[mi][3],
                            bf[ni][0], bf[ni][1]);
        }
        if (s + 3 < NS) stage(s + 3);
    }

    #pragma unroll
    for (int mi = 0; mi < 4; mi++) {
        #pragma unroll
        for (int ni = 0; ni < 8; ni++) {
            const int row0 = blockIdx.y * 128 + wm + mi * 16 + g;
            const int col  = blockIdx.x * 128 + wn + ni * 8 + 2 * tq;
            #pragma unroll
            for (int half_i = 0; half_i < 2; half_i++) {
                const int row = row0 + half_i * 8;
                float v0 = acc[mi][ni][half_i * 2 + 0];
                float v1 = acc[mi][ni][half_i * 2 + 1];
                if (MODE == 0) {
                    __half2 hv = __floats2half2_rn(v0, v1);
                    *(uint32_t*)((__half*)Cout + (size_t)row * N + col) = *(uint32_t*)&hv;
                }
                if (MODE == 1) {
                    v0 = fmaxf(v0 + bias[col], 0.f);
                    v1 = fmaxf(v1 + bias[col + 1], 0.f);
                    __half2 hv = __floats2half2_rn(v0, v1);
                    *(uint32_t*)((__half*)Cout + (size_t)row * N + col) = *(uint32_t*)&hv;
                }
                if (MODE == 2) {
                    v0 += bias[col]     + res[(size_t)row * N + col];
                    v1 += bias[col + 1] + res[(size_t)row * N + col + 1];
                    *(float2*)((float*)Cout + (size_t)row * N + col) = make_float2(v0, v1);
                }
            }
        }
    }
}

// ---------------------------------------------------------------------------
// fp16 flash attention, Q-tile 128 rows, no-max softmax, register-resident P,
// KV triple-buffered (no end-of-tile barrier). ex2-folded softmax: one
// FMUL-imm + MUFU per score. Rotating buffer index (no % in loop).
// Block = 128 q rows, 4 warps x 32 rows (2 m16 tiles). d=64, T=1024.
// smem halves: Qs[128][72], Ks[3][64][72], Vs[3][64][72] = 73728 B (2 CTAs/SM)
// ---------------------------------------------------------------------------
#define QP 72
__global__ __launch_bounds__(128, 2) void attn_h_kernel(
    const __half* __restrict__ QKV, const float* __restrict__ res,
    float* __restrict__ O)
{
    extern __shared__ __half sh[];
    __half* Qs = sh;                  // [128][QP]
    __half* Ks = sh + 128 * QP;       // [3][64][QP]
    __half* Vs = Ks + 3 * 64 * QP;    // [3][64][QP]

    const int tid  = threadIdx.x;
    const int warp = tid >> 5, lane = tid & 31;
    const int g = lane >> 2, tq = lane & 3;
    const int bh = blockIdx.y, b = bh >> 4, h = bh & 15;
    const int qt = blockIdx.x;        // 0..7
    const int wrow = warp * 32;

    const uint32_t qb = (uint32_t)__cvta_generic_to_shared(Qs);
    const uint32_t kbase = (uint32_t)__cvta_generic_to_shared(Ks);
    const uint32_t vbase = (uint32_t)__cvta_generic_to_shared(Vs);

    const __half* Qg = QKV + ((size_t)(b * 1024 + qt * 128)) * 3072 + h * 64;
    const __half* Kg = QKV + (size_t)b * 1024 * 3072 + 1024 + h * 64;
    const __half* Vg = QKV + (size_t)b * 1024 * 3072 + 2048 + h * 64;

    auto stageKVbuf = [&](int t, int buf) {
        const uint32_t kb0 = kbase + (uint32_t)(buf * 64 * QP) * 2;
        const uint32_t vb0 = vbase + (uint32_t)(buf * 64 * QP) * 2;
        #pragma unroll
        for (int i = 0; i < 4; i++) {
            int id = tid + (i << 7);
            int r = id >> 3, c = (id & 7) * 8;
            cp16(kb0 + (uint32_t)(r * QP + c) * 2, Kg + (size_t)(t * 64 + r) * 3072 + c);
        }
        #pragma unroll
        for (int i = 0; i < 4; i++) {
            int id = tid + (i << 7);
            int r = id >> 3, c = (id & 7) * 8;
            cp16(vb0 + (uint32_t)(r * QP + c) * 2, Vg + (size_t)(t * 64 + r) * 3072 + c);
        }
        CP_COMMIT();
    };

    // stage Q (128 rows; group 0), then KV tile 0 (group 1)
    #pragma unroll
    for (int i = 0; i < 8; i++) {
        int id = tid + (i << 7);
        int r = id >> 3, c = (id & 7) * 8;
        cp16(qb + (uint32_t)(r * QP + c) * 2, Qg + (size_t)r * 3072 + c);
    }
    CP_COMMIT();
    stageKVbuf(0, 0);

    asm volatile("cp.async.wait_group 1;\n" ::: "memory");   // Q landed
    __syncthreads();
    uint32_t qf[2][4][4];
    #pragma unroll
    for (int mi = 0; mi < 2; mi++)
        #pragma unroll
        for (int ks = 0; ks < 4; ks++) {
            uint32_t addr = qb +
                (uint32_t)((wrow + mi * 16 + (lane & 15)) * QP + ks * 16 + (lane >> 4) * 8) * 2;
            ldsm_x4(qf[mi][ks][0], qf[mi][ks][1], qf[mi][ks][2], qf[mi][ks][3], addr);
        }

    float l[2][2] = {};
    float oacc[2][8][4] = {};

    int buf = 0, nbuf = 1;   // rotating triple-buffer indices
    for (int st = 0; st < 16; st++) {
        if (st + 1 < 16) {
            stageKVbuf(st + 1, nbuf);
            asm volatile("cp.async.wait_group 1;\n" ::: "memory");
        } else {
            asm volatile("cp.async.wait_group 0;\n" ::: "memory");
        }
        __syncthreads();   // buffer st visible to all warps

        const uint32_t kb0 = kbase + (uint32_t)(buf * 64 * QP) * 2;
        const uint32_t vb0 = vbase + (uint32_t)(buf * 64 * QP) * 2;

        // S = Q K^T (m32 x n64, k64)
        float sacc[2][8][4] = {};
        #pragma unroll
        for (int ks = 0; ks < 4; ks++) {
            const int kb = ks * 16;
            uint32_t bf[8][2];
            #pragma unroll
            for (int nj = 0; nj < 4; nj++) {
                uint32_t r0, r1, r2, r3;
                uint32_t addr = kb0 +
                    (uint32_t)((nj * 16 + (lane & 15)) * QP + kb + (lane >> 4) * 8) * 2;
                ldsm_x4(r0, r1, r2, r3, addr);
                bf[nj * 2][0] = r0; bf[nj * 2][1] = r2;
                bf[nj * 2 + 1][0] = r1; bf[nj * 2 + 1][1] = r3;
            }
            #pragma unroll
            for (int mi = 0; mi < 2; mi++)
                #pragma unroll
                for (int ni = 0; ni < 8; ni++)
                    mma_f16(sacc[mi][ni], qf[mi][ks][0], qf[mi][ks][1],
                            qf[mi][ks][2], qf[mi][ks][3], bf[ni][0], bf[ni][1]);
        }

        // softmax: p = exp(s/32) = ex2(s * log2e/32) — one FMUL-imm + MUFU.
        uint32_t ph[2][8][2];
        #pragma unroll
        for (int mi = 0; mi < 2; mi++) {
            #pragma unroll
            for (int ni = 0; ni < 8; ni++) {
                float p0 = ex2f(sacc[mi][ni][0] * EXP_SCALE);
                float p1 = ex2f(sacc[mi][ni][1] * EXP_SCALE);
                float p2 = ex2f(sacc[mi][ni][2] * EXP_SCALE);
                float p3 = ex2f(sacc[mi][ni][3] * EXP_SCALE);
                l[mi][0] += p0 + p1;
                l[mi][1] += p2 + p3;
                __half2 hp0 = __floats2half2_rn(p0, p1);
                __half2 hp1 = __floats2half2_rn(p2, p3);
                ph[mi][ni][0] = *(uint32_t*)&hp0;
                ph[mi][ni][1] = *(uint32_t*)&hp1;
            }
        }

        // O += P V (A-frags from registers)
        #pragma unroll
        for (int j = 0; j < 4; j++) {
            const int kb = j * 16;
            uint32_t bf[8][2];
            #pragma unroll
            for (int nj = 0; nj < 4; nj++) {
                uint32_t addr = vb0 +
                    (uint32_t)((kb + (lane & 15)) * QP + nj * 16 + (lane >> 4) * 8) * 2;
                ldsm_x4t(bf[nj * 2][0], bf[nj * 2][1],
                         bf[nj * 2 + 1][0], bf[nj * 2 + 1][1], addr);
            }
            #pragma unroll
            for (int mi = 0; mi < 2; mi++) {
                #pragma unroll
                for (int ni = 0; ni < 8; ni++)
                    mma_f16(oacc[mi][ni],
                            ph[mi][2 * j][0], ph[mi][2 * j][1],
                            ph[mi][2 * j + 1][0], ph[mi][2 * j + 1][1],
                            bf[ni][0], bf[ni][1]);
            }
        }
        // rotate buffers (no modulo)
        buf = nbuf;
        nbuf = (nbuf == 2) ? 0 : nbuf + 1;
        // no end-of-tile barrier: triple buffer guarantees reuse distance
    }

    // reduce row sums across the quad (tq axis)
    #pragma unroll
    for (int mi = 0; mi < 2; mi++)
        #pragma unroll
        for (int hf = 0; hf < 2; hf++) {
            #pragma unroll
            for (int off = 1; off < 4; off <<= 1)
                l[mi][hf] += __shfl_xor_sync(0xffffffffu, l[mi][hf], off);
        }

    const size_t obase = ((size_t)(b * 1024 + qt * 128 + wrow)) * 1024 + h * 64;
    #pragma unroll
    for (int mi = 0; mi < 2; mi++) {
        const float inv0 = 1.f / l[mi][0], inv1 = 1.f / l[mi][1];
        #pragma unroll
        for (int ni = 0; ni < 8; ni++) {
            const int col = ni * 8 + 2 * tq;
            const size_t a0 = obase + (size_t)(mi * 16 + g) * 1024 + col;
            const size_t a1 = obase + (size_t)(mi * 16 + g + 8) * 1024 + col;
            float2 r0 = *(const float2*)(res + a0);
            float2 r1 = *(const float2*)(res + a1);
            *(float2*)(O + a0) = make_float2(oacc[mi][ni][0] * inv0 + r0.x,
                                             oacc[mi][ni][1] * inv0 + r0.y);
            *(float2*)(O + a1) = make_float2(oacc[mi][ni][2] * inv1 + r1.x,
                                             oacc[mi][ni][3] * inv1 + r1.y);
        }
    }
}

// ---------------------------------------------------------------------------
// Host launch
// ---------------------------------------------------------------------------
extern "C" void kernel_launch(void* const* d_in, const int* in_sizes, int n_in,
                              void* d_out, int out_size)
{
    (void)in_sizes; (void)n_in; (void)out_size;
    const float* x   = (const float*)d_in[0];
    const float* Wq1 = (const float*)d_in[1];
    const float* Wk1 = (const float*)d_in[2];
    const float* Wv1 = (const float*)d_in[3];
    const float* Wq2 = (const float*)d_in[4];
    const float* Wk2 = (const float*)d_in[5];
    const float* Wv2 = (const float*)d_in[6];
    const float* g1  = (const float*)d_in[7];
    const float* b1  = (const float*)d_in[8];
    const float* g2  = (const float*)d_in[9];
    const float* b2  = (const float*)d_in[10];
    const float* g3  = (const float*)d_in[11];
    const float* b3  = (const float*)d_in[12];
    const float* W1  = (const float*)d_in[13];
    const float* bf1 = (const float*)d_in[14];
    const float* W2  = (const float*)d_in[15];
    const float* bf2 = (const float*)d_in[16];
    float* out = (float*)d_out;

    __half *ln, *qkv, *h1, *wt, *w1, *w2;
    float *x1, *x2;
    cudaGetSymbolAddress((void**)&ln,  g_ln);
    cudaGetSymbolAddress((void**)&qkv, g_qkv);
    cudaGetSymbolAddress((void**)&x1,  g_x1);
    cudaGetSymbolAddress((void**)&x2,  g_x2);
    cudaGetSymbolAddress((void**)&h1,  g_h1);
    cudaGetSymbolAddress((void**)&wt,  g_wt);
    cudaGetSymbolAddress((void**)&w1,  g_w1);
    cudaGetSymbolAddress((void**)&w2,  g_w2);

    const int GEMM_SMEM = 4 * STG * 2;                 // 75776
    const int ATTN_SMEM = (128 + 6 * 64) * QP * 2;     // 73728
    cudaFuncSetAttribute(hgemm_kernel<0>, cudaFuncAttributeMaxDynamicSharedMemorySize, GEMM_SMEM);
    cudaFuncSetAttribute(hgemm_kernel<1>, cudaFuncAttributeMaxDynamicSharedMemorySize, GEMM_SMEM);
    cudaFuncSetAttribute(hgemm_kernel<2>, cudaFuncAttributeMaxDynamicSharedMemorySize, GEMM_SMEM);
    cudaFuncSetAttribute(attn_h_kernel,   cudaFuncAttributeMaxDynamicSharedMemorySize, ATTN_SMEM);

    const int M = TOK, C = CDIM;
    const size_t LSZ = (size_t)C * 3072;

    dim3 gW(4096, 8);
    wprep_kernel<<<gW, 256>>>(Wq1, Wk1, Wv1, Wq2, Wk2, Wv2, wt,
                              (const float4*)W1, (const float4*)W2, w1, w2);

    dim3 gQKV(3072 / 128, M / 128);    // (24, 32)
    dim3 gMLP1(HID / 128, M / 128);    // (32, 32)
    dim3 gMLP2(C / 128, M / 128);      // (8, 32)
    dim3 gAttn(8, 64);                 // 8 q-tiles of 128 x (B*H)

    // --- MSA block 1 ---
    ln_kernel<<<TOK, 256>>>(x, g1, b1, ln);
    hgemm_kernel<0><<<gQKV, 128, GEMM_SMEM>>>(ln, wt + 0 * LSZ, nullptr, nullptr, qkv, M, 3072, C);
    attn_h_kernel<<<gAttn, 128, ATTN_SMEM>>>(qkv, x, x1);      // x1 = x + msa1

    // --- MSA block 2 ---
    ln_kernel<<<TOK, 256>>>(x1, g2, b2, ln);
    hgemm_kernel<0><<<gQKV, 128, GEMM_SMEM>>>(ln, wt + 1 * LSZ, nullptr, nullptr, qkv, M, 3072, C);
    attn_h_kernel<<<gAttn, 128, ATTN_SMEM>>>(qkv, x1, x2);     // x2 = x1 + msa2

    // --- MLP block ---
    ln_kernel<<<TOK, 256>>>(x2, g3, b3, ln);
    hgemm_kernel<1><<<gMLP1, 128, GEMM_SMEM>>>(ln, w1, bf1, nullptr, h1, M, HID, C);
    hgemm_kernel<2><<<gMLP2, 128, GEMM_SMEM>>>(h1, w2, bf2, x2, out, M, C, HID);
}

// round 17
// speedup vs baseline: 1.1711x; 1.0014x over previous
#include <cuda_runtime.h>
#include <cuda_fp16.h>
#include <math.h>
#include <stdint.h>

// ---------------------------------------------------------------------------
// Scratch (device globals; no allocation allowed)
// ---------------------------------------------------------------------------
#define TOK 4096              // B*T = 4*1024
#define CDIM 1024
#define HID 4096

__device__ __half g_ln [TOK * CDIM];
__device__ __half g_qkv[TOK * 3072];
__device__ float  g_x1 [TOK * CDIM];
__device__ float  g_x2 [TOK * CDIM];
__device__ __half g_h1 [TOK * HID];
__device__ __half g_wt [2 * CDIM * 3072];   // per layer: [C=1024][3072] = Wq|Wk|Wv
__device__ __half g_w1 [CDIM * HID];
__device__ __half g_w2 [HID * CDIM];

// ---------------------------------------------------------------------------
// helpers
// ---------------------------------------------------------------------------
__device__ __forceinline__ void mma_f16(float c[4],
    uint32_t a0, uint32_t a1, uint32_t a2, uint32_t a3,
    uint32_t b0, uint32_t b1)
{
    asm volatile(
        "mma.sync.aligned.m16n8k16.row.col.f32.f16.f16.f32 "
        "{%0,%1,%2,%3}, {%4,%5,%6,%7}, {%8,%9}, {%0,%1,%2,%3};\n"
        : "+f"(c[0]), "+f"(c[1]), "+f"(c[2]), "+f"(c[3])
        : "r"(a0), "r"(a1), "r"(a2), "r"(a3), "r"(b0), "r"(b1));
}

__device__ __forceinline__ void ldsm_x4(uint32_t& r0, uint32_t& r1,
                                        uint32_t& r2, uint32_t& r3, uint32_t addr)
{
    asm volatile("ldmatrix.sync.aligned.m8n8.x4.shared.b16 {%0,%1,%2,%3}, [%4];"
        : "=r"(r0), "=r"(r1), "=r"(r2), "=r"(r3) : "r"(addr));
}
__device__ __forceinline__ void ldsm_x4t(uint32_t& r0, uint32_t& r1,
                                         uint32_t& r2, uint32_t& r3, uint32_t addr)
{
    asm volatile("ldmatrix.sync.aligned.m8n8.x4.trans.shared.b16 {%0,%1,%2,%3}, [%4];"
        : "=r"(r0), "=r"(r1), "=r"(r2), "=r"(r3) : "r"(addr));
}

__device__ __forceinline__ void cp16(uint32_t dst_smem, const void* src) {
    asm volatile("cp.async.cg.shared.global [%0], [%1], 16;\n"
        :: "r"(dst_smem), "l"(src));
}
#define CP_COMMIT() asm volatile("cp.async.commit_group;\n" ::: "memory")

// ex2 on packed half2 — two exponentials per MUFU
__device__ __forceinline__ uint32_t ex2_h2(uint32_t x) {
    uint32_t y;
    asm("ex2.approx.f16x2 %0, %1;" : "=r"(y) : "r"(x));
    return y;
}
#define EXP_SCALE 0.04508422f   // log2(e) / 32
#define ONES_H2   0x3C003C00u   // half2(1.0, 1.0)

// ---------------------------------------------------------------------------
// Fused preprocessing: grid (4096, 8)
//   y<6 : per-head transpose [H=16,C=1024,d=64] -> half cols of [C][3072]
//   y=6 : W1 float4 -> half    y=7 : W2 float4 -> half
// ---------------------------------------------------------------------------
__global__ void wprep_kernel(
    const float* __restrict__ s0, const float* __restrict__ s1,
    const float* __restrict__ s2, const float* __restrict__ s3,
    const float* __restrict__ s4, const float* __restrict__ s5,
    __half* __restrict__ wt,
    const float4* __restrict__ W1, const float4* __restrict__ W2,
    __half* __restrict__ w1, __half* __restrict__ w2)
{
    const int which = blockIdx.y;
    if (which < 6) {
        const float* srcs[6] = {s0, s1, s2, s3, s4, s5};
        const float* W = srcs[which];
        __half* Wt = wt + (size_t)(which / 3) * (CDIM * 3072) + (which % 3) * 1024;
        int idx = blockIdx.x * 256 + threadIdx.x;       // 0 .. 1M-1
        int dd = idx & 63;
        int c  = (idx >> 6) & 1023;
        int h  = idx >> 16;
        Wt[(size_t)c * 3072 + h * 64 + dd] = __float2half(W[idx]);
    } else {
        int j = blockIdx.x * 256 + threadIdx.x;         // 0 .. 1M-1 (float4s)
        float4 v = (which == 6) ? W1[j] : W2[j];
        __half2 h0 = __floats2half2_rn(v.x, v.y);
        __half2 h1 = __floats2half2_rn(v.z, v.w);
        uint2 u = make_uint2(*(uint32_t*)&h0, *(uint32_t*)&h1);
        if (which == 6) ((uint2*)w1)[j] = u; else ((uint2*)w2)[j] = u;
    }
}

// ---------------------------------------------------------------------------
// LayerNorm: one block per row of 1024; half output
// ---------------------------------------------------------------------------
__global__ __launch_bounds__(256) void ln_kernel(
    const float* __restrict__ x, const float* __restrict__ g,
    const float* __restrict__ b, __half* __restrict__ out)
{
    __shared__ float red[2][8];
    const int row = blockIdx.x;
    const int tid = threadIdx.x;
    const float4 xv = ((const float4*)(x + (size_t)row * 1024))[tid];
    float s  = xv.x + xv.y + xv.z + xv.w;
    float ss = xv.x*xv.x + xv.y*xv.y + xv.z*xv.z + xv.w*xv.w;
    #pragma unroll
    for (int off = 16; off; off >>= 1) {
        s  += __shfl_xor_sync(0xffffffffu, s,  off);
        ss += __shfl_xor_sync(0xffffffffu, ss, off);
    }
    const int warp = tid >> 5, lane = tid & 31;
    if (lane == 0) { red[0][warp] = s; red[1][warp] = ss; }
    __syncthreads();
    float st = 0.f, sst = 0.f;
    #pragma unroll
    for (int i = 0; i < 8; i++) { st += red[0][i]; sst += red[1][i]; }
    const float mean = st * (1.f / 1024.f);
    const float var  = sst * (1.f / 1024.f) - mean * mean;
    const float inv  = rsqrtf(var + 1e-5f);
    const float4 gv = ((const float4*)g)[tid];
    const float4 bv = ((const float4*)b)[tid];
    __half2 h0 = __floats2half2_rn((xv.x - mean) * inv * gv.x + bv.x,
                                   (xv.y - mean) * inv * gv.y + bv.y);
    __half2 h1 = __floats2half2_rn((xv.z - mean) * inv * gv.z + bv.z,
                                   (xv.w - mean) * inv * gv.w + bv.w);
    ((uint2*)(out + (size_t)row * 1024))[tid] =
        make_uint2(*(uint32_t*)&h0, *(uint32_t*)&h1);
}

// ---------------------------------------------------------------------------
// fp16 tensor-core GEMM, cp.async 4-stage, ldmatrix fragments. (R11 winner,
// FROZEN — prefetch after compute block, no mainloop changes.)
//   C[M,N] = A[M,K] @ B[K,N]  (+ epilogue)
//   MODE 0: plain -> half out   MODE 1: +bias, relu -> half out
//   MODE 2: +bias +res -> float out
// CTA tile 128x128, BK=32, 128 thr = 4 warps (2Mx2N), warp tile 64x64.
// 2 CTAs/SM; 4-stage pipeline (3 tiles in flight).
// smem (halves): 4 stages x (A[128][40] + B[32][136]) = 75776 B
// ---------------------------------------------------------------------------
#define AP   40
#define BP   136
#define ASTG (128 * AP)
#define BSTG (32 * BP)
#define STG  (ASTG + BSTG)
template<int MODE>
__global__ __launch_bounds__(128, 2) void hgemm_kernel(
    const __half* __restrict__ A, const __half* __restrict__ B,
    const float* __restrict__ bias, const float* __restrict__ res,
    void* __restrict__ Cout, int M, int N, int K)
{
    extern __shared__ __half sh[];
    const int tid  = threadIdx.x;
    const int warp = tid >> 5, lane = tid & 31;
    const int g  = lane >> 2, tq = lane & 3;
    const int wm = (warp >> 1) * 64;     // 0,64  (warp covers 64 M rows)
    const int wn = (warp & 1) * 64;      // 0,64

    const __half* Ag = A + (size_t)(blockIdx.y * 128) * K;
    const __half* Bg = B + blockIdx.x * 128;
    const uint32_t sb = (uint32_t)__cvta_generic_to_shared(sh);

    auto stage = [&](int s) {
        const int k0 = s * 32;
        const uint32_t ab = sb + (uint32_t)((s & 3) * STG) * 2;
        const uint32_t bb = ab + ASTG * 2;
        #pragma unroll
        for (int i = 0; i < 4; i++) {               // A: 128 rows x 4 chunks
            int id = tid + (i << 7);
            int r = id >> 2, c = (id & 3) * 8;
            cp16(ab + (uint32_t)(r * AP + c) * 2, Ag + (size_t)r * K + k0 + c);
        }
        #pragma unroll
        for (int i = 0; i < 4; i++) {               // B: 32 rows x 16 chunks
            int id = tid + (i << 7);
            int r = id >> 4, c = (id & 15) * 8;
            cp16(bb + (uint32_t)(r * BP + c) * 2, Bg + (size_t)(k0 + r) * N + c);
        }
        CP_COMMIT();
    };

    float acc[4][8][4] = {};
    stage(0); stage(1); stage(2);

    const int NS = K / 32;
    for (int s = 0; s < NS; s++) {
        if (s < NS - 2)       asm volatile("cp.async.wait_group 2;\n" ::: "memory");
        else if (s == NS - 2) asm volatile("cp.async.wait_group 1;\n" ::: "memory");
        else                  asm volatile("cp.async.wait_group 0;\n" ::: "memory");
        __syncthreads();

        const uint32_t ab = sb + (uint32_t)((s & 3) * STG) * 2;
        const uint32_t bb = ab + ASTG * 2;
        #pragma unroll
        for (int ks = 0; ks < 2; ks++) {
            const int kb = ks * 16;
            uint32_t af[4][4];
            #pragma unroll
            for (int mi = 0; mi < 4; mi++) {
                uint32_t addr = ab +
                    (uint32_t)((wm + mi * 16 + (lane & 15)) * AP + kb + (lane >> 4) * 8) * 2;
                ldsm_x4(af[mi][0], af[mi][1], af[mi][2], af[mi][3], addr);
            }
            uint32_t bf[8][2];
            #pragma unroll
            for (int nj = 0; nj < 4; nj++) {
                uint32_t addr = bb +
                    (uint32_t)((kb + (lane & 15)) * BP + wn + nj * 16 + (lane >> 4) * 8) * 2;
                ldsm_x4t(bf[nj * 2][0], bf[nj * 2][1],
                         bf[nj * 2 + 1][0], bf[nj * 2 + 1][1], addr);
            }
            #pragma unroll
            for (int mi = 0; mi < 4; mi++)
                #pragma unroll
                for (int ni = 0; ni < 8; ni++)
                    mma_f16(acc[mi][ni], af[mi][0], af[mi][1], af[mi][2], af[mi][3],
                            bf[ni][0], bf[ni][1]);
        }
        if (s + 3 < NS) stage(s + 3);
    }

    #pragma unroll
    for (int mi = 0; mi < 4; mi++) {
        #pragma unroll
        for (int ni = 0; ni < 8; ni++) {
            const int row0 = blockIdx.y * 128 + wm + mi * 16 + g;
            const int col  = blockIdx.x * 128 + wn + ni * 8 + 2 * tq;
            #pragma unroll
            for (int half_i = 0; half_i < 2; half_i++) {
                const int row = row0 + half_i * 8;
                float v0 = acc[mi][ni][half_i * 2 + 0];
                float v1 = acc[mi][ni][half_i * 2 + 1];
                if (MODE == 0) {
                    __half2 hv = __floats2half2_rn(v0, v1);
                    *(uint32_t*)((__half*)Cout + (size_t)row * N + col) = *(uint32_t*)&hv;
                }
                if (MODE == 1) {
                    v0 = fmaxf(v0 + bias[col], 0.f);
                    v1 = fmaxf(v1 + bias[col + 1], 0.f);
                    __half2 hv = __floats2half2_rn(v0, v1);
                    *(uint32_t*)((__half*)Cout + (size_t)row * N + col) = *(uint32_t*)&hv;
                }
                if (MODE == 2) {
                    v0 += bias[col]     + res[(size_t)row * N + col];
                    v1 += bias[col + 1] + res[(size_t)row * N + col + 1];
                    *(float2*)((float*)Cout + (size_t)row * N + col) = make_float2(v0, v1);
                }
            }
        }
    }
}

// ---------------------------------------------------------------------------
// fp16 flash attention, Q-tile 128 rows, no-max softmax, register-resident P,
// KV triple-buffered (no end-of-tile barrier).
// NEW: half2 softmax (F2FP pack -> HMUL2 scale -> ex2.f16x2) and l computed
// by ones-MMA (l = P @ 1) on the tensor pipe — removes the fp32 FMUL/MUFU/FADD
// scalar block and the final cross-quad shuffle reduction.
// Block = 128 q rows, 4 warps x 32 rows (2 m16 tiles). d=64, T=1024.
// smem halves: Qs[128][72], Ks[3][64][72], Vs[3][64][72] = 73728 B (2 CTAs/SM)
// ---------------------------------------------------------------------------
#define QP 72
__global__ __launch_bounds__(128, 2) void attn_h_kernel(
    const __half* __restrict__ QKV, const float* __restrict__ res,
    float* __restrict__ O)
{
    extern __shared__ __half sh[];
    __half* Qs = sh;                  // [128][QP]
    __half* Ks = sh + 128 * QP;       // [3][64][QP]
    __half* Vs = Ks + 3 * 64 * QP;    // [3][64][QP]

    const int tid  = threadIdx.x;
    const int warp = tid >> 5, lane = tid & 31;
    const int g = lane >> 2, tq = lane & 3;
    const int bh = blockIdx.y, b = bh >> 4, h = bh & 15;
    const int qt = blockIdx.x;        // 0..7
    const int wrow = warp * 32;

    const uint32_t qb = (uint32_t)__cvta_generic_to_shared(Qs);
    const uint32_t kbase = (uint32_t)__cvta_generic_to_shared(Ks);
    const uint32_t vbase = (uint32_t)__cvta_generic_to_shared(Vs);

    const __half* Qg = QKV + ((size_t)(b * 1024 + qt * 128)) * 3072 + h * 64;
    const __half* Kg = QKV + (size_t)b * 1024 * 3072 + 1024 + h * 64;
    const __half* Vg = QKV + (size_t)b * 1024 * 3072 + 2048 + h * 64;

    const __half2 sc2 = __half2half2(__float2half_rn(EXP_SCALE));
    const uint32_t sc2u = *(const uint32_t*)&sc2;

    auto stageKVbuf = [&](int t, int buf) {
        const uint32_t kb0 = kbase + (uint32_t)(buf * 64 * QP) * 2;
        const uint32_t vb0 = vbase + (uint32_t)(buf * 64 * QP) * 2;
        #pragma unroll
        for (int i = 0; i < 4; i++) {
            int id = tid + (i << 7);
            int r = id >> 3, c = (id & 7) * 8;
            cp16(kb0 + (uint32_t)(r * QP + c) * 2, Kg + (size_t)(t * 64 + r) * 3072 + c);
        }
        #pragma unroll
        for (int i = 0; i < 4; i++) {
            int id = tid + (i << 7);
            int r = id >> 3, c = (id & 7) * 8;
            cp16(vb0 + (uint32_t)(r * QP + c) * 2, Vg + (size_t)(t * 64 + r) * 3072 + c);
        }
        CP_COMMIT();
    };

    // stage Q (128 rows; group 0), then KV tile 0 (group 1)
    #pragma unroll
    for (int i = 0; i < 8; i++) {
        int id = tid + (i << 7);
        int r = id >> 3, c = (id & 7) * 8;
        cp16(qb + (uint32_t)(r * QP + c) * 2, Qg + (size_t)r * 3072 + c);
    }
    CP_COMMIT();
    stageKVbuf(0, 0);

    asm volatile("cp.async.wait_group 1;\n" ::: "memory");   // Q landed
    __syncthreads();
    uint32_t qf[2][4][4];
    #pragma unroll
    for (int mi = 0; mi < 2; mi++)
        #pragma unroll
        for (int ks = 0; ks < 4; ks++) {
            uint32_t addr = qb +
                (uint32_t)((wrow + mi * 16 + (lane & 15)) * QP + ks * 16 + (lane >> 4) * 8) * 2;
            ldsm_x4(qf[mi][ks][0], qf[mi][ks][1], qf[mi][ks][2], qf[mi][ks][3], addr);
        }

    float lacc[2][4] = {};            // ones-mma accumulator: c0=row g, c2=row g+8
    float oacc[2][8][4] = {};

    int buf = 0, nbuf = 1;   // rotating triple-buffer indices
    for (int st = 0; st < 16; st++) {
        if (st + 1 < 16) {
            stageKVbuf(st + 1, nbuf);
            asm volatile("cp.async.wait_group 1;\n" ::: "memory");
        } else {
            asm volatile("cp.async.wait_group 0;\n" ::: "memory");
        }
        __syncthreads();   // buffer st visible to all warps

        const uint32_t kb0 = kbase + (uint32_t)(buf * 64 * QP) * 2;
        const uint32_t vb0 = vbase + (uint32_t)(buf * 64 * QP) * 2;

        // S = Q K^T (m32 x n64, k64)
        float sacc[2][8][4] = {};
        #pragma unroll
        for (int ks = 0; ks < 4; ks++) {
            const int kb = ks * 16;
            uint32_t bf[8][2];
            #pragma unroll
            for (int nj = 0; nj < 4; nj++) {
                uint32_t r0, r1, r2, r3;
                uint32_t addr = kb0 +
                    (uint32_t)((nj * 16 + (lane & 15)) * QP + kb + (lane >> 4) * 8) * 2;
                ldsm_x4(r0, r1, r2, r3, addr);
                bf[nj * 2][0] = r0; bf[nj * 2][1] = r2;
                bf[nj * 2 + 1][0] = r1; bf[nj * 2 + 1][1] = r3;
            }
            #pragma unroll
            for (int mi = 0; mi < 2; mi++)
                #pragma unroll
                for (int ni = 0; ni < 8; ni++)
                    mma_f16(sacc[mi][ni], qf[mi][ks][0], qf[mi][ks][1],
                            qf[mi][ks][2], qf[mi][ks][3], bf[ni][0], bf[ni][1]);
        }

        // half2 softmax: pack -> HMUL2 scale -> ex2.f16x2. P stays in regs.
        uint32_t ph[2][8][2];
        #pragma unroll
        for (int mi = 0; mi < 2; mi++) {
            #pragma unroll
            for (int ni = 0; ni < 8; ni++) {
                __half2 ha = __floats2half2_rn(sacc[mi][ni][0], sacc[mi][ni][1]);
                __half2 hb = __floats2half2_rn(sacc[mi][ni][2], sacc[mi][ni][3]);
                __half2 sa = __hmul2(ha, *(const __half2*)&sc2u);
                __half2 sb = __hmul2(hb, *(const __half2*)&sc2u);
                ph[mi][ni][0] = ex2_h2(*(uint32_t*)&sa);
                ph[mi][ni][1] = ex2_h2(*(uint32_t*)&sb);
            }
        }

        // O += P V (A-frags from registers) ; l += P @ 1 (ones-mma)
        #pragma unroll
        for (int j = 0; j < 4; j++) {
            const int kb = j * 16;
            uint32_t bf[8][2];
            #pragma unroll
            for (int nj = 0; nj < 4; nj++) {
                uint32_t addr = vb0 +
                    (uint32_t)((kb + (lane & 15)) * QP + nj * 16 + (lane >> 4) * 8) * 2;
                ldsm_x4t(bf[nj * 2][0], bf[nj * 2][1],
                         bf[nj * 2 + 1][0], bf[nj * 2 + 1][1], addr);
            }
            #pragma unroll
            for (int mi = 0; mi < 2; mi++) {
                #pragma unroll
                for (int ni = 0; ni < 8; ni++)
                    mma_f16(oacc[mi][ni],
                            ph[mi][2 * j][0], ph[mi][2 * j][1],
                            ph[mi][2 * j + 1][0], ph[mi][2 * j + 1][1],
                            bf[ni][0], bf[ni][1]);
                mma_f16(lacc[mi],
                        ph[mi][2 * j][0], ph[mi][2 * j][1],
                        ph[mi][2 * j + 1][0], ph[mi][2 * j + 1][1],
                        ONES_H2, ONES_H2);
            }
        }
        // rotate buffers (no modulo)
        buf = nbuf;
        nbuf = (nbuf == 2) ? 0 : nbuf + 1;
        // no end-of-tile barrier: triple buffer guarantees reuse distance
    }

    // l comes fully reduced out of the ones-mma (no shuffles needed)
    const size_t obase = ((size_t)(b * 1024 + qt * 128 + wrow)) * 1024 + h * 64;
    #pragma unroll
    for (int mi = 0; mi < 2; mi++) {
        const float inv0 = 1.f / lacc[mi][0], inv1 = 1.f / lacc[mi][2];
        #pragma unroll
        for (int ni = 0; ni < 8; ni++) {
            const int col = ni * 8 + 2 * tq;
            const size_t a0 = obase + (size_t)(mi * 16 + g) * 1024 + col;
            const size_t a1 = obase + (size_t)(mi * 16 + g + 8) * 1024 + col;
            float2 r0 = *(const float2*)(res + a0);
            float2 r1 = *(const float2*)(res + a1);
            *(float2*)(O + a0) = make_float2(oacc[mi][ni][0] * inv0 + r0.x,
                                             oacc[mi][ni][1] * inv0 + r0.y);
            *(float2*)(O + a1) = make_float2(oacc[mi][ni][2] * inv1 + r1.x,
                                             oacc[mi][ni][3] * inv1 + r1.y);
        }
    }
}

// ---------------------------------------------------------------------------
// Host launch
// ---------------------------------------------------------------------------
extern "C" void kernel_launch(void* const* d_in, const int* in_sizes, int n_in,
                              void* d_out, int out_size)
{
    (void)in_sizes; (void)n_in; (void)out_size;
    const float* x   = (const float*)d_in[0];
    const float* Wq1 = (const float*)d_in[1];
    const float* Wk1 = (const float*)d_in[2];
    const float* Wv1 = (const float*)d_in[3];
    const float* Wq2 = (const float*)d_in[4];
    const float* Wk2 = (const float*)d_in[5];
    const float* Wv2 = (const float*)d_in[6];
    const float* g1  = (const float*)d_in[7];
    const float* b1  = (const float*)d_in[8];
    const float* g2  = (const float*)d_in[9];
    const float* b2  = (const float*)d_in[10];
    const float* g3  = (const float*)d_in[11];
    const float* b3  = (const float*)d_in[12];
    const float* W1  = (const float*)d_in[13];
    const float* bf1 = (const float*)d_in[14];
    const float* W2  = (const float*)d_in[15];
    const float* bf2 = (const float*)d_in[16];
    float* out = (float*)d_out;

    __half *ln, *qkv, *h1, *wt, *w1, *w2;
    float *x1, *x2;
    cudaGetSymbolAddress((void**)&ln,  g_ln);
    cudaGetSymbolAddress((void**)&qkv, g_qkv);
    cudaGetSymbolAddress((void**)&x1,  g_x1);
    cudaGetSymbolAddress((void**)&x2,  g_x2);
    cudaGetSymbolAddress((void**)&h1,  g_h1);
    cudaGetSymbolAddress((void**)&wt,  g_wt);
    cudaGetSymbolAddress((void**)&w1,  g_w1);
    cudaGetSymbolAddress((void**)&w2,  g_w2);

    const int GEMM_SMEM = 4 * STG * 2;                 // 75776
    const int ATTN_SMEM = (128 + 6 * 64) * QP * 2;     // 73728
    cudaFuncSetAttribute(hgemm_kernel<0>, cudaFuncAttributeMaxDynamicSharedMemorySize, GEMM_SMEM);
    cudaFuncSetAttribute(hgemm_kernel<1>, cudaFuncAttributeMaxDynamicSharedMemorySize, GEMM_SMEM);
    cudaFuncSetAttribute(hgemm_kernel<2>, cudaFuncAttributeMaxDynamicSharedMemorySize, GEMM_SMEM);
    cudaFuncSetAttribute(attn_h_kernel,   cudaFuncAttributeMaxDynamicSharedMemorySize, ATTN_SMEM);

    const int M = TOK, C = CDIM;
    const size_t LSZ = (size_t)C * 3072;

    dim3 gW(4096, 8);
    wprep_kernel<<<gW, 256>>>(Wq1, Wk1, Wv1, Wq2, Wk2, Wv2, wt,
                              (const float4*)W1, (const float4*)W2, w1, w2);

    dim3 gQKV(3072 / 128, M / 128);    // (24, 32)
    dim3 gMLP1(HID / 128, M / 128);    // (32, 32)
    dim3 gMLP2(C / 128, M / 128);      // (8, 32)
    dim3 gAttn(8, 64);                 // 8 q-tiles of 128 x (B*H)

    // --- MSA block 1 ---
    ln_kernel<<<TOK, 256>>>(x, g1, b1, ln);
    hgemm_kernel<0><<<gQKV, 128, GEMM_SMEM>>>(ln, wt + 0 * LSZ, nullptr, nullptr, qkv, M, 3072, C);
    attn_h_kernel<<<gAttn, 128, ATTN_SMEM>>>(qkv, x, x1);      // x1 = x + msa1

    // --- MSA block 2 ---
    ln_kernel<<<TOK, 256>>>(x1, g2, b2, ln);
    hgemm_kernel<0><<<gQKV, 128, GEMM_SMEM>>>(ln, wt + 1 * LSZ, nullptr, nullptr, qkv, M, 3072, C);
    attn_h_kernel<<<gAttn, 128, ATTN_SMEM>>>(qkv, x1, x2);     // x2 = x1 + msa2

    // --- MLP block ---
    ln_kernel<<<TOK, 256>>>(x2, g3, b3, ln);
    hgemm_kernel<1><<<gMLP1, 128, GEMM_SMEM>>>(ln, w1, bf1, nullptr, h1, M, HID, C);
    hgemm_kernel<2><<<gMLP2, 128, GEMM_SMEM>>>(h1, w2, bf2, x2, out, M, C, HID);
}